// round 1
// baseline (speedup 1.0000x reference)
#include <cuda_runtime.h>
#include <cstdint>

// EdgeBlock: out[e] = relu(concat(cell[src[e]], cell[dst[e]], edge[e]) @ W1 + b1) @ W2 + b2
// E = 800000, d_node = d_edge = d_hid = d_out = 128, d_in = 384. All fp32.
//
// Strategy: fused two-layer GEMM, 64 edges per block, 256 threads,
// 4x8 outputs/thread, packed fma.rn.f32x2 accumulation (2 FMA/instr).

typedef unsigned long long ull;

__device__ __forceinline__ void fma2(ull &d, ull a, ull b) {
    asm("fma.rn.f32x2 %0, %1, %2, %0;" : "+l"(d) : "l"(a), "l"(b));
}
__device__ __forceinline__ ull pack2(float lo, float hi) {
    ull r;
    asm("mov.b64 %0, {%1, %2};" : "=l"(r) : "f"(lo), "f"(hi));
    return r;
}
__device__ __forceinline__ float2 unpack2(ull v) {
    float2 f;
    asm("mov.b64 {%0, %1}, %2;" : "=f"(f.x), "=f"(f.y) : "l"(v));
    return f;
}

#define TILE_E 64
#define NTHREADS 256
#define AS_STRIDE 68   // 64 + pad, multiple of 4 floats (16B aligned rows)
#define HS_STRIDE 68

// shared memory layout (bytes):
//   phase 1:  As[64][68]  @ 0        (17408)
//             Ws[64][128] @ 17408    (32768)   -> phase1 end = 50176
//   phase 2:  Hs[128][68] @ 0        (34816)
//             W2s[128][128] @ 34816  (65536)   -> phase2 end = 100352
//   always:   s_src[64] @ 100352, s_dst[64] @ 100608  -> total 100864
#define SMEM_BYTES 100864

__global__ void __launch_bounds__(NTHREADS, 2)
edgeblock_kernel(const float* __restrict__ cell,
                 const float* __restrict__ edge,
                 const float* __restrict__ W1,
                 const float* __restrict__ b1,
                 const float* __restrict__ W2,
                 const float* __restrict__ b2,
                 const int*   __restrict__ eidx,
                 float* __restrict__ out,
                 int E)
{
    extern __shared__ char sm[];
    float* As  = reinterpret_cast<float*>(sm);
    float* Ws  = reinterpret_cast<float*>(sm + 17408);
    float* Hs  = reinterpret_cast<float*>(sm);
    float* W2s = reinterpret_cast<float*>(sm + 34816);
    int* s_src = reinterpret_cast<int*>(sm + 100352);
    int* s_dst = reinterpret_cast<int*>(sm + 100608);

    const int tid = threadIdx.x;
    const int e0  = blockIdx.x * TILE_E;

    // ---- load edge indices for this tile ----
    if (tid < 64) {
        int e = e0 + tid; if (e >= E) e = E - 1;
        s_src[tid] = eidx[e];
    } else if (tid < 128) {
        int r = tid - 64;
        int e = e0 + r; if (e >= E) e = E - 1;
        s_dst[r] = eidx[E + e];
    }

    const int ty = tid >> 4;      // 0..15
    const int tx = tid & 15;      // 0..15
    const int r0 = ty * 4;        // edge-row base of this thread's 4 rows
    const int c0 = tx * 8;        // output-col base of this thread's 8 cols

    // A-load assignment: thread covers float4-column c4 of 4 rows
    const int c4    = tid & 15;   // 0..15 (float4 column within 64-wide chunk)
    const int rbase = tid >> 4;   // 0..15

    // ---- init gemm1 accumulators with b1 ----
    ull acc[16];
    {
        float4 blo = *reinterpret_cast<const float4*>(&b1[c0]);
        float4 bhi = *reinterpret_cast<const float4*>(&b1[c0 + 4]);
        ull p0 = pack2(blo.x, blo.y), p1 = pack2(blo.z, blo.w);
        ull p2 = pack2(bhi.x, bhi.y), p3 = pack2(bhi.z, bhi.w);
#pragma unroll
        for (int r = 0; r < 4; ++r) {
            acc[r * 4 + 0] = p0; acc[r * 4 + 1] = p1;
            acc[r * 4 + 2] = p2; acc[r * 4 + 3] = p3;
        }
    }

    // ---- GEMM1: [64 x 384] @ [384 x 128], K streamed in 6 chunks of 64 ----
#pragma unroll 1
    for (int ch = 0; ch < 6; ++ch) {
        __syncthreads();   // previous chunk fully consumed / indices ready

        // load A tile (gathered), store transposed As[k][row]
#pragma unroll
        for (int m = 0; m < 4; ++m) {
            int row = m * 16 + rbase;
            int e   = e0 + row;
            int eL  = (e < E) ? e : (E - 1);
            const float* base;
            if (ch < 2)      base = cell + (size_t)s_src[row] * 128 + ch * 64;
            else if (ch < 4) base = cell + (size_t)s_dst[row] * 128 + (ch - 2) * 64;
            else             base = edge + (size_t)eL * 128 + (ch - 4) * 64;
            float4 v = *reinterpret_cast<const float4*>(base + c4 * 4);
            float vv[4] = {v.x, v.y, v.z, v.w};
            // lane-rotated scatter to reduce STS bank conflicts
#pragma unroll
            for (int j = 0; j < 4; ++j) {
                int jj = (j + c4) & 3;
                As[(c4 * 4 + jj) * AS_STRIDE + row] = vv[jj];
            }
        }

        // stage W1 chunk: Ws[64][128]
        {
            const float4* wsrc = reinterpret_cast<const float4*>(W1 + (size_t)ch * 64 * 128);
            float4* wdst = reinterpret_cast<float4*>(Ws);
#pragma unroll
            for (int m = 0; m < 8; ++m)
                wdst[tid + m * 256] = wsrc[tid + m * 256];
        }
        __syncthreads();

        // compute 64 k-steps
#pragma unroll 16
        for (int k = 0; k < 64; ++k) {
            float4 av = *reinterpret_cast<const float4*>(&As[k * AS_STRIDE + r0]);
            ulonglong2 w0 = *reinterpret_cast<const ulonglong2*>(&Ws[k * 128 + c0]);
            ulonglong2 w1 = *reinterpret_cast<const ulonglong2*>(&Ws[k * 128 + c0 + 4]);
            const float* ap = reinterpret_cast<const float*>(&av);
#pragma unroll
            for (int r = 0; r < 4; ++r) {
                ull a = pack2(ap[r], ap[r]);
                fma2(acc[r * 4 + 0], a, w0.x);
                fma2(acc[r * 4 + 1], a, w0.y);
                fma2(acc[r * 4 + 2], a, w1.x);
                fma2(acc[r * 4 + 3], a, w1.y);
            }
        }
    }

    __syncthreads();   // gemm1 reads done; smem now reused for phase 2

    // ---- ReLU, write h transposed Hs[c][row]; stage W2; re-init acc with b2 ----
    {
        float h[4][8];
#pragma unroll
        for (int r = 0; r < 4; ++r)
#pragma unroll
            for (int p = 0; p < 4; ++p) {
                float2 f = unpack2(acc[r * 4 + p]);
                h[r][2 * p]     = fmaxf(f.x, 0.0f);
                h[r][2 * p + 1] = fmaxf(f.y, 0.0f);
            }
#pragma unroll
        for (int cc = 0; cc < 8; ++cc) {
            float4 q = make_float4(h[0][cc], h[1][cc], h[2][cc], h[3][cc]);
            *reinterpret_cast<float4*>(&Hs[(c0 + cc) * HS_STRIDE + r0]) = q;
        }

        const float4* wsrc = reinterpret_cast<const float4*>(W2);
        float4* wdst = reinterpret_cast<float4*>(W2s);
#pragma unroll
        for (int m = 0; m < 16; ++m)
            wdst[tid + m * 256] = wsrc[tid + m * 256];

        float4 blo = *reinterpret_cast<const float4*>(&b2[c0]);
        float4 bhi = *reinterpret_cast<const float4*>(&b2[c0 + 4]);
        ull p0 = pack2(blo.x, blo.y), p1 = pack2(blo.z, blo.w);
        ull p2 = pack2(bhi.x, bhi.y), p3 = pack2(bhi.z, bhi.w);
#pragma unroll
        for (int r = 0; r < 4; ++r) {
            acc[r * 4 + 0] = p0; acc[r * 4 + 1] = p1;
            acc[r * 4 + 2] = p2; acc[r * 4 + 3] = p3;
        }
    }
    __syncthreads();

    // ---- GEMM2: [64 x 128] @ [128 x 128] ----
#pragma unroll 16
    for (int k = 0; k < 128; ++k) {
        float4 av = *reinterpret_cast<const float4*>(&Hs[k * HS_STRIDE + r0]);
        ulonglong2 w0 = *reinterpret_cast<const ulonglong2*>(&W2s[k * 128 + c0]);
        ulonglong2 w1 = *reinterpret_cast<const ulonglong2*>(&W2s[k * 128 + c0 + 4]);
        const float* ap = reinterpret_cast<const float*>(&av);
#pragma unroll
        for (int r = 0; r < 4; ++r) {
            ull a = pack2(ap[r], ap[r]);
            fma2(acc[r * 4 + 0], a, w0.x);
            fma2(acc[r * 4 + 1], a, w0.y);
            fma2(acc[r * 4 + 2], a, w1.x);
            fma2(acc[r * 4 + 3], a, w1.y);
        }
    }

    // ---- epilogue: coalesced STG.128 ----
#pragma unroll
    for (int r = 0; r < 4; ++r) {
        int e = e0 + r0 + r;
        if (e < E) {
            float2 f0 = unpack2(acc[r * 4 + 0]);
            float2 f1 = unpack2(acc[r * 4 + 1]);
            float2 f2 = unpack2(acc[r * 4 + 2]);
            float2 f3 = unpack2(acc[r * 4 + 3]);
            float4 o0 = make_float4(f0.x, f0.y, f1.x, f1.y);
            float4 o1 = make_float4(f2.x, f2.y, f3.x, f3.y);
            float* op = out + (size_t)e * 128 + c0;
            *reinterpret_cast<float4*>(op)     = o0;
            *reinterpret_cast<float4*>(op + 4) = o1;
        }
    }
}

extern "C" void kernel_launch(void* const* d_in, const int* in_sizes, int n_in,
                              void* d_out, int out_size) {
    const float* cell = (const float*)d_in[0];   // [50000,128]
    const float* edge = (const float*)d_in[1];   // [E,128]
    const float* W1   = (const float*)d_in[2];   // [384,128]
    const float* b1   = (const float*)d_in[3];   // [128]
    const float* W2   = (const float*)d_in[4];   // [128,128]
    const float* b2   = (const float*)d_in[5];   // [128]
    const int*   eidx = (const int*)d_in[6];     // [2,E]
    float* out = (float*)d_out;

    int E = in_sizes[6] / 2;

    cudaFuncSetAttribute(edgeblock_kernel,
                         cudaFuncAttributeMaxDynamicSharedMemorySize, SMEM_BYTES);

    int grid = (E + TILE_E - 1) / TILE_E;
    edgeblock_kernel<<<grid, NTHREADS, SMEM_BYTES>>>(
        cell, edge, W1, b1, W2, b2, eidx, out, E);
}

// round 2
// speedup vs baseline: 1.0023x; 1.0023x over previous
#include <cuda_runtime.h>
#include <cstdint>

// EdgeBlock: out[e] = relu(concat(cell[src[e]], cell[dst[e]], edge[e]) @ W1 + b1) @ W2 + b2
// E = 800000, d_node = d_edge = d_hid = d_out = 128, d_in = 384. All fp32.
//
// Strategy: fused two-layer GEMM, 64 edges per block, 256 threads,
// 4x8 outputs/thread, packed fma.rn.f32x2 accumulation (2 FMA/instr).

typedef unsigned long long ull;

__device__ __forceinline__ void fma2(ull &d, ull a, ull b) {
    asm("fma.rn.f32x2 %0, %1, %2, %0;" : "+l"(d) : "l"(a), "l"(b));
}
__device__ __forceinline__ ull pack2(float lo, float hi) {
    ull r;
    asm("mov.b64 %0, {%1, %2};" : "=l"(r) : "f"(lo), "f"(hi));
    return r;
}
__device__ __forceinline__ float2 unpack2(ull v) {
    float2 f;
    asm("mov.b64 {%0, %1}, %2;" : "=f"(f.x), "=f"(f.y) : "l"(v));
    return f;
}

#define TILE_E 64
#define NTHREADS 256
#define AS_STRIDE 68   // 64 + pad, multiple of 4 floats (16B aligned rows)
#define HS_STRIDE 68

// shared memory layout (bytes):
//   phase 1:  As[64][68]  @ 0        (17408)
//             Ws[64][128] @ 17408    (32768)   -> phase1 end = 50176
//   phase 2:  Hs[128][68] @ 0        (34816)
//             W2s[128][128] @ 34816  (65536)   -> phase2 end = 100352
//   always:   s_src[64] @ 100352, s_dst[64] @ 100608  -> total 100864
#define SMEM_BYTES 100864

__global__ void __launch_bounds__(NTHREADS, 2)
edgeblock_kernel(const float* __restrict__ cell,
                 const float* __restrict__ edge,
                 const float* __restrict__ W1,
                 const float* __restrict__ b1,
                 const float* __restrict__ W2,
                 const float* __restrict__ b2,
                 const int*   __restrict__ eidx,
                 float* __restrict__ out,
                 int E)
{
    extern __shared__ char sm[];
    float* As  = reinterpret_cast<float*>(sm);
    float* Ws  = reinterpret_cast<float*>(sm + 17408);
    float* Hs  = reinterpret_cast<float*>(sm);
    float* W2s = reinterpret_cast<float*>(sm + 34816);
    int* s_src = reinterpret_cast<int*>(sm + 100352);
    int* s_dst = reinterpret_cast<int*>(sm + 100608);

    const int tid = threadIdx.x;
    const int e0  = blockIdx.x * TILE_E;

    // ---- load edge indices for this tile ----
    if (tid < 64) {
        int e = e0 + tid; if (e >= E) e = E - 1;
        s_src[tid] = eidx[e];
    } else if (tid < 128) {
        int r = tid - 64;
        int e = e0 + r; if (e >= E) e = E - 1;
        s_dst[r] = eidx[E + e];
    }

    const int ty = tid >> 4;      // 0..15
    const int tx = tid & 15;      // 0..15
    const int r0 = ty * 4;        // edge-row base of this thread's 4 rows
    const int c0 = tx * 8;        // output-col base of this thread's 8 cols

    // A-load assignment: thread covers float4-column c4 of 4 rows
    const int c4    = tid & 15;   // 0..15 (float4 column within 64-wide chunk)
    const int rbase = tid >> 4;   // 0..15

    // ---- init gemm1 accumulators with b1 ----
    ull acc[16];
    {
        float4 blo = *reinterpret_cast<const float4*>(&b1[c0]);
        float4 bhi = *reinterpret_cast<const float4*>(&b1[c0 + 4]);
        ull p0 = pack2(blo.x, blo.y), p1 = pack2(blo.z, blo.w);
        ull p2 = pack2(bhi.x, bhi.y), p3 = pack2(bhi.z, bhi.w);
#pragma unroll
        for (int r = 0; r < 4; ++r) {
            acc[r * 4 + 0] = p0; acc[r * 4 + 1] = p1;
            acc[r * 4 + 2] = p2; acc[r * 4 + 3] = p3;
        }
    }

    // ---- GEMM1: [64 x 384] @ [384 x 128], K streamed in 6 chunks of 64 ----
#pragma unroll 1
    for (int ch = 0; ch < 6; ++ch) {
        __syncthreads();   // previous chunk fully consumed / indices ready

        // load A tile (gathered), store transposed As[k][row]
#pragma unroll
        for (int m = 0; m < 4; ++m) {
            int row = m * 16 + rbase;
            int e   = e0 + row;
            int eL  = (e < E) ? e : (E - 1);
            const float* base;
            if (ch < 2)      base = cell + (size_t)s_src[row] * 128 + ch * 64;
            else if (ch < 4) base = cell + (size_t)s_dst[row] * 128 + (ch - 2) * 64;
            else             base = edge + (size_t)eL * 128 + (ch - 4) * 64;
            float4 v = *reinterpret_cast<const float4*>(base + c4 * 4);
            float vv[4] = {v.x, v.y, v.z, v.w};
            // lane-rotated scatter to reduce STS bank conflicts
#pragma unroll
            for (int j = 0; j < 4; ++j) {
                int jj = (j + c4) & 3;
                As[(c4 * 4 + jj) * AS_STRIDE + row] = vv[jj];
            }
        }

        // stage W1 chunk: Ws[64][128]
        {
            const float4* wsrc = reinterpret_cast<const float4*>(W1 + (size_t)ch * 64 * 128);
            float4* wdst = reinterpret_cast<float4*>(Ws);
#pragma unroll
            for (int m = 0; m < 8; ++m)
                wdst[tid + m * 256] = wsrc[tid + m * 256];
        }
        __syncthreads();

        // compute 64 k-steps
#pragma unroll 16
        for (int k = 0; k < 64; ++k) {
            float4 av = *reinterpret_cast<const float4*>(&As[k * AS_STRIDE + r0]);
            ulonglong2 w0 = *reinterpret_cast<const ulonglong2*>(&Ws[k * 128 + c0]);
            ulonglong2 w1 = *reinterpret_cast<const ulonglong2*>(&Ws[k * 128 + c0 + 4]);
            const float* ap = reinterpret_cast<const float*>(&av);
#pragma unroll
            for (int r = 0; r < 4; ++r) {
                ull a = pack2(ap[r], ap[r]);
                fma2(acc[r * 4 + 0], a, w0.x);
                fma2(acc[r * 4 + 1], a, w0.y);
                fma2(acc[r * 4 + 2], a, w1.x);
                fma2(acc[r * 4 + 3], a, w1.y);
            }
        }
    }

    __syncthreads();   // gemm1 reads done; smem now reused for phase 2

    // ---- ReLU, write h transposed Hs[c][row]; stage W2; re-init acc with b2 ----
    {
        float h[4][8];
#pragma unroll
        for (int r = 0; r < 4; ++r)
#pragma unroll
            for (int p = 0; p < 4; ++p) {
                float2 f = unpack2(acc[r * 4 + p]);
                h[r][2 * p]     = fmaxf(f.x, 0.0f);
                h[r][2 * p + 1] = fmaxf(f.y, 0.0f);
            }
#pragma unroll
        for (int cc = 0; cc < 8; ++cc) {
            float4 q = make_float4(h[0][cc], h[1][cc], h[2][cc], h[3][cc]);
            *reinterpret_cast<float4*>(&Hs[(c0 + cc) * HS_STRIDE + r0]) = q;
        }

        const float4* wsrc = reinterpret_cast<const float4*>(W2);
        float4* wdst = reinterpret_cast<float4*>(W2s);
#pragma unroll
        for (int m = 0; m < 16; ++m)
            wdst[tid + m * 256] = wsrc[tid + m * 256];

        float4 blo = *reinterpret_cast<const float4*>(&b2[c0]);
        float4 bhi = *reinterpret_cast<const float4*>(&b2[c0 + 4]);
        ull p0 = pack2(blo.x, blo.y), p1 = pack2(blo.z, blo.w);
        ull p2 = pack2(bhi.x, bhi.y), p3 = pack2(bhi.z, bhi.w);
#pragma unroll
        for (int r = 0; r < 4; ++r) {
            acc[r * 4 + 0] = p0; acc[r * 4 + 1] = p1;
            acc[r * 4 + 2] = p2; acc[r * 4 + 3] = p3;
        }
    }
    __syncthreads();

    // ---- GEMM2: [64 x 128] @ [128 x 128] ----
#pragma unroll 16
    for (int k = 0; k < 128; ++k) {
        float4 av = *reinterpret_cast<const float4*>(&Hs[k * HS_STRIDE + r0]);
        ulonglong2 w0 = *reinterpret_cast<const ulonglong2*>(&W2s[k * 128 + c0]);
        ulonglong2 w1 = *reinterpret_cast<const ulonglong2*>(&W2s[k * 128 + c0 + 4]);
        const float* ap = reinterpret_cast<const float*>(&av);
#pragma unroll
        for (int r = 0; r < 4; ++r) {
            ull a = pack2(ap[r], ap[r]);
            fma2(acc[r * 4 + 0], a, w0.x);
            fma2(acc[r * 4 + 1], a, w0.y);
            fma2(acc[r * 4 + 2], a, w1.x);
            fma2(acc[r * 4 + 3], a, w1.y);
        }
    }

    // ---- epilogue: coalesced STG.128 ----
#pragma unroll
    for (int r = 0; r < 4; ++r) {
        int e = e0 + r0 + r;
        if (e < E) {
            float2 f0 = unpack2(acc[r * 4 + 0]);
            float2 f1 = unpack2(acc[r * 4 + 1]);
            float2 f2 = unpack2(acc[r * 4 + 2]);
            float2 f3 = unpack2(acc[r * 4 + 3]);
            float4 o0 = make_float4(f0.x, f0.y, f1.x, f1.y);
            float4 o1 = make_float4(f2.x, f2.y, f3.x, f3.y);
            float* op = out + (size_t)e * 128 + c0;
            *reinterpret_cast<float4*>(op)     = o0;
            *reinterpret_cast<float4*>(op + 4) = o1;
        }
    }
}

extern "C" void kernel_launch(void* const* d_in, const int* in_sizes, int n_in,
                              void* d_out, int out_size) {
    const float* cell = (const float*)d_in[0];   // [50000,128]
    const float* edge = (const float*)d_in[1];   // [E,128]
    const float* W1   = (const float*)d_in[2];   // [384,128]
    const float* b1   = (const float*)d_in[3];   // [128]
    const float* W2   = (const float*)d_in[4];   // [128,128]
    const float* b2   = (const float*)d_in[5];   // [128]
    const int*   eidx = (const int*)d_in[6];     // [2,E]
    float* out = (float*)d_out;

    int E = in_sizes[6] / 2;

    cudaFuncSetAttribute(edgeblock_kernel,
                         cudaFuncAttributeMaxDynamicSharedMemorySize, SMEM_BYTES);

    int grid = (E + TILE_E - 1) / TILE_E;
    edgeblock_kernel<<<grid, NTHREADS, SMEM_BYTES>>>(
        cell, edge, W1, b1, W2, b2, eidx, out, E);
}

// round 4
// speedup vs baseline: 2.0114x; 2.0067x over previous
#include <cuda_runtime.h>
#include <cuda_bf16.h>
#include <cstdint>

// EdgeBlock: out = relu(concat(cell[src],cell[dst],edge) @ W1 + b1) @ W2 + b2
// bf16 3-term split (hi*hi + lo*hi + hi*lo) on mma.sync.m16n8k16 (sm_80+ ISA,
// legal on virtual sm_103 target), fp32 accumulation.

#define THREADS 256
#define TILE_M  128
#define RS      136                 // bf16 elements per smem row (128 + 8 pad)
#define TILE_ELEMS (128 * RS)       // one 128x128 tile (padded)
#define TILE_BYTES (TILE_ELEMS * 2)
#define SMEM_BYTES (4 * TILE_BYTES) // A_hi, A_lo, W_hi, W_lo = 139264

// pre-split weights, row-major k x n (same layout as inputs)
__device__ __nv_bfloat16 g_W1_hi[384 * 128];
__device__ __nv_bfloat16 g_W1_lo[384 * 128];
__device__ __nv_bfloat16 g_W2_hi[128 * 128];
__device__ __nv_bfloat16 g_W2_lo[128 * 128];

// ---------------- helpers ----------------
__device__ __forceinline__ uint32_t smem_u32(const void* p) {
    uint32_t a;
    asm("{ .reg .u64 t; cvta.to.shared.u64 t, %1; cvt.u32.u64 %0, t; }" : "=r"(a) : "l"(p));
    return a;
}
__device__ __forceinline__ void ldm_x4(uint32_t* r, uint32_t addr) {
    asm volatile("ldmatrix.sync.aligned.m8n8.x4.shared.b16 {%0,%1,%2,%3}, [%4];"
                 : "=r"(r[0]), "=r"(r[1]), "=r"(r[2]), "=r"(r[3]) : "r"(addr));
}
__device__ __forceinline__ void ldm_x4_t(uint32_t* r, uint32_t addr) {
    asm volatile("ldmatrix.sync.aligned.m8n8.x4.trans.shared.b16 {%0,%1,%2,%3}, [%4];"
                 : "=r"(r[0]), "=r"(r[1]), "=r"(r[2]), "=r"(r[3]) : "r"(addr));
}
__device__ __forceinline__ void mma16816(float* d, const uint32_t* a, const uint32_t* b) {
    asm volatile(
        "mma.sync.aligned.m16n8k16.row.col.f32.bf16.bf16.f32 "
        "{%0,%1,%2,%3}, {%4,%5,%6,%7}, {%8,%9}, {%0,%1,%2,%3};"
        : "+f"(d[0]), "+f"(d[1]), "+f"(d[2]), "+f"(d[3])
        : "r"(a[0]), "r"(a[1]), "r"(a[2]), "r"(a[3]), "r"(b[0]), "r"(b[1]));
}

// 8 k16-steps of the 128x128x128 3-term split GEMM for one warp
__device__ __forceinline__ void gemm_chunk(uint32_t Ah, uint32_t Al,
                                           uint32_t Wh, uint32_t Wl,
                                           float acc[2][8][4],
                                           int wm, int wn, int lane)
{
    const int lr = lane & 15;        // row within 16
    const int lc = (lane >> 4) * 8;  // 8-col group
#pragma unroll 1
    for (int kk = 0; kk < 8; ++kk) {
        uint32_t ah[2][4], al[2][4];
#pragma unroll
        for (int t = 0; t < 2; ++t) {
            uint32_t ao = ((wm * 32 + t * 16 + lr) * RS + kk * 16 + lc) * 2;
            ldm_x4(ah[t], Ah + ao);
            ldm_x4(al[t], Al + ao);
        }
        uint32_t bh[4][4], bl[4][4];
#pragma unroll
        for (int g = 0; g < 4; ++g) {
            uint32_t bo = ((kk * 16 + lr) * RS + wn * 64 + g * 16 + lc) * 2;
            ldm_x4_t(bh[g], Wh + bo);
            ldm_x4_t(bl[g], Wl + bo);
        }
#pragma unroll
        for (int t = 0; t < 2; ++t)
#pragma unroll
            for (int g = 0; g < 4; ++g) {
                mma16816(acc[t][2 * g],     ah[t], &bh[g][0]);
                mma16816(acc[t][2 * g + 1], ah[t], &bh[g][2]);
                mma16816(acc[t][2 * g],     al[t], &bh[g][0]);
                mma16816(acc[t][2 * g + 1], al[t], &bh[g][2]);
                mma16816(acc[t][2 * g],     ah[t], &bl[g][0]);
                mma16816(acc[t][2 * g + 1], ah[t], &bl[g][2]);
            }
    }
}

// ---------------- weight prep: hi/lo bf16 split (row-major, no transpose) ----------------
__global__ void prep_kernel(const float* __restrict__ W1, const float* __restrict__ W2) {
    int i = blockIdx.x * blockDim.x + threadIdx.x;
    if (i < 384 * 128) {
        float v = W1[i];
        __nv_bfloat16 h = __float2bfloat16(v);
        g_W1_hi[i] = h;
        g_W1_lo[i] = __float2bfloat16(v - __bfloat162float(h));
    }
    if (i < 128 * 128) {
        float v = W2[i];
        __nv_bfloat16 h = __float2bfloat16(v);
        g_W2_hi[i] = h;
        g_W2_lo[i] = __float2bfloat16(v - __bfloat162float(h));
    }
}

// ---------------- main fused kernel ----------------
__global__ void __launch_bounds__(THREADS, 1)
edgeblock_mma(const float* __restrict__ cell,
              const float* __restrict__ edge,
              const float* __restrict__ b1,
              const float* __restrict__ b2,
              const int*   __restrict__ eidx,
              float* __restrict__ out,
              int E)
{
    extern __shared__ __align__(128) __nv_bfloat16 sm[];
    __nv_bfloat16* Ah = sm;
    __nv_bfloat16* Al = sm + TILE_ELEMS;
    __nv_bfloat16* Wh = sm + 2 * TILE_ELEMS;
    __nv_bfloat16* Wl = sm + 3 * TILE_ELEMS;
    const uint32_t sb   = smem_u32(sm);
    const uint32_t Ah_u = sb;
    const uint32_t Al_u = sb + TILE_BYTES;
    const uint32_t Wh_u = sb + 2 * TILE_BYTES;
    const uint32_t Wl_u = sb + 3 * TILE_BYTES;

    const int tid = threadIdx.x, wid = tid >> 5, lane = tid & 31;
    const int wm = wid >> 1, wn = wid & 1;
    const int e0 = blockIdx.x * TILE_M;

    float acc[2][8][4];
#pragma unroll
    for (int t = 0; t < 2; ++t)
#pragma unroll
        for (int j = 0; j < 8; ++j)
#pragma unroll
            for (int c = 0; c < 4; ++c) acc[t][j][c] = 0.0f;

    // ===== GEMM1: 3 K-chunks of 128 (src-gather, dst-gather, edge rows) =====
#pragma unroll 1
    for (int ch = 0; ch < 3; ++ch) {
        // gather + hi/lo split A chunk: idx = row*32 + c4 (float4 col)
#pragma unroll 1
        for (int i = 0; i < 16; ++i) {
            int idx = i * 256 + tid;
            int row = idx >> 5, c4 = idx & 31;
            int e = e0 + row; int eL = (e < E) ? e : (E - 1);
            const float* base;
            if (ch == 0)      base = cell + (size_t)eidx[eL] * 128;
            else if (ch == 1) base = cell + (size_t)eidx[E + eL] * 128;
            else              base = edge + (size_t)eL * 128;
            float4 v = reinterpret_cast<const float4*>(base)[c4];
            __nv_bfloat162 h0 = __float22bfloat162_rn(make_float2(v.x, v.y));
            __nv_bfloat162 h1 = __float22bfloat162_rn(make_float2(v.z, v.w));
            __nv_bfloat162 l0 = __float22bfloat162_rn(make_float2(
                v.x - __bfloat162float(h0.x), v.y - __bfloat162float(h0.y)));
            __nv_bfloat162 l1 = __float22bfloat162_rn(make_float2(
                v.z - __bfloat162float(h1.x), v.w - __bfloat162float(h1.y)));
            uint64_t hh = ((uint64_t)*reinterpret_cast<uint32_t*>(&h1) << 32) |
                           *reinterpret_cast<uint32_t*>(&h0);
            uint64_t ll = ((uint64_t)*reinterpret_cast<uint32_t*>(&l1) << 32) |
                           *reinterpret_cast<uint32_t*>(&l0);
            int off = row * RS + c4 * 4;   // 8B aligned (RS even, c4*4 mult of 4)
            *reinterpret_cast<uint64_t*>(Ah + off) = hh;
            *reinterpret_cast<uint64_t*>(Al + off) = ll;
        }
        // stage W1 chunk [128k x 128n] hi/lo: idx = row*64 + c2 (u32 col)
        {
            const uint32_t* wh = reinterpret_cast<const uint32_t*>(g_W1_hi + (size_t)ch * 128 * 128);
            const uint32_t* wl = reinterpret_cast<const uint32_t*>(g_W1_lo + (size_t)ch * 128 * 128);
#pragma unroll
            for (int i = 0; i < 32; ++i) {
                int idx = i * 256 + tid;
                int row = idx >> 6, c2 = idx & 63;
                int off = row * RS + c2 * 2;
                *reinterpret_cast<uint32_t*>(Wh + off) = wh[idx];
                *reinterpret_cast<uint32_t*>(Wl + off) = wl[idx];
            }
        }
        __syncthreads();
        gemm_chunk(Ah_u, Al_u, Wh_u, Wl_u, acc, wm, wn, lane);
        __syncthreads();   // compute done before next chunk overwrites tiles
    }

    // ===== epilogue1: h = relu(acc + b1), split hi/lo back into A tiles; stage W2 =====
    {
        const int colb = wn * 64 + (lane & 3) * 2;
        const int rowb = wm * 32 + (lane >> 2);
#pragma unroll
        for (int t = 0; t < 2; ++t)
#pragma unroll
            for (int j = 0; j < 8; ++j) {
                int col = colb + j * 8;
                float bx = __ldg(&b1[col]), by = __ldg(&b1[col + 1]);
#pragma unroll
                for (int half = 0; half < 2; ++half) {
                    int row = rowb + t * 16 + half * 8;
                    float x = fmaxf(acc[t][j][2 * half]     + bx, 0.0f);
                    float y = fmaxf(acc[t][j][2 * half + 1] + by, 0.0f);
                    __nv_bfloat162 h2 = __float22bfloat162_rn(make_float2(x, y));
                    __nv_bfloat162 l2 = __float22bfloat162_rn(make_float2(
                        x - __bfloat162float(h2.x), y - __bfloat162float(h2.y)));
                    int off = row * RS + col;
                    *reinterpret_cast<uint32_t*>(Ah + off) = *reinterpret_cast<uint32_t*>(&h2);
                    *reinterpret_cast<uint32_t*>(Al + off) = *reinterpret_cast<uint32_t*>(&l2);
                }
            }
        // stage W2 hi/lo
        const uint32_t* wh = reinterpret_cast<const uint32_t*>(g_W2_hi);
        const uint32_t* wl = reinterpret_cast<const uint32_t*>(g_W2_lo);
#pragma unroll
        for (int i = 0; i < 32; ++i) {
            int idx = i * 256 + tid;
            int row = idx >> 6, c2 = idx & 63;
            int off = row * RS + c2 * 2;
            *reinterpret_cast<uint32_t*>(Wh + off) = wh[idx];
            *reinterpret_cast<uint32_t*>(Wl + off) = wl[idx];
        }
        // zero accumulators for GEMM2
#pragma unroll
        for (int t = 0; t < 2; ++t)
#pragma unroll
            for (int j = 0; j < 8; ++j)
#pragma unroll
                for (int c = 0; c < 4; ++c) acc[t][j][c] = 0.0f;
    }
    __syncthreads();

    // ===== GEMM2: [128 x 128] @ W2 =====
    gemm_chunk(Ah_u, Al_u, Wh_u, Wl_u, acc, wm, wn, lane);

    // ===== epilogue2: + b2, store =====
    {
        const int colb = wn * 64 + (lane & 3) * 2;
        const int rowb = wm * 32 + (lane >> 2);
#pragma unroll
        for (int t = 0; t < 2; ++t)
#pragma unroll
            for (int j = 0; j < 8; ++j) {
                int col = colb + j * 8;
                float bx = __ldg(&b2[col]), by = __ldg(&b2[col + 1]);
#pragma unroll
                for (int half = 0; half < 2; ++half) {
                    int row = rowb + t * 16 + half * 8;
                    int e = e0 + row;
                    if (e < E) {
                        float2 o = make_float2(acc[t][j][2 * half] + bx,
                                               acc[t][j][2 * half + 1] + by);
                        *reinterpret_cast<float2*>(out + (size_t)e * 128 + col) = o;
                    }
                }
            }
    }
}

extern "C" void kernel_launch(void* const* d_in, const int* in_sizes, int n_in,
                              void* d_out, int out_size) {
    const float* cell = (const float*)d_in[0];   // [50000,128]
    const float* edge = (const float*)d_in[1];   // [E,128]
    const float* W1   = (const float*)d_in[2];   // [384,128]
    const float* b1   = (const float*)d_in[3];   // [128]
    const float* W2   = (const float*)d_in[4];   // [128,128]
    const float* b2   = (const float*)d_in[5];   // [128]
    const int*   eidx = (const int*)d_in[6];     // [2,E]
    float* out = (float*)d_out;

    int E = in_sizes[6] / 2;

    prep_kernel<<<(384 * 128 + 255) / 256, 256>>>(W1, W2);

    cudaFuncSetAttribute(edgeblock_mma,
                         cudaFuncAttributeMaxDynamicSharedMemorySize, SMEM_BYTES);
    int grid = (E + TILE_M - 1) / TILE_M;
    edgeblock_mma<<<grid, THREADS, SMEM_BYTES>>>(cell, edge, b1, b2, eidx, out, E);
}

// round 5
// speedup vs baseline: 2.0127x; 1.0006x over previous
#include <cuda_runtime.h>
#include <cuda_bf16.h>
#include <cstdint>

// EdgeBlock: out = relu(concat(cell[src],cell[dst],edge) @ W1 + b1) @ W2 + b2
// bf16 3-term split (hi*hi + lo*hi + hi*lo) on mma.sync.m16n8k16 (sm_80+ ISA,
// legal on virtual sm_103 target), fp32 accumulation.

#define THREADS 256
#define TILE_M  128
#define RS      136                 // bf16 elements per smem row (128 + 8 pad)
#define TILE_ELEMS (128 * RS)       // one 128x128 tile (padded)
#define TILE_BYTES (TILE_ELEMS * 2)
#define SMEM_BYTES (4 * TILE_BYTES) // A_hi, A_lo, W_hi, W_lo = 139264

// pre-split weights, row-major k x n (same layout as inputs)
__device__ __nv_bfloat16 g_W1_hi[384 * 128];
__device__ __nv_bfloat16 g_W1_lo[384 * 128];
__device__ __nv_bfloat16 g_W2_hi[128 * 128];
__device__ __nv_bfloat16 g_W2_lo[128 * 128];

// ---------------- helpers ----------------
__device__ __forceinline__ uint32_t smem_u32(const void* p) {
    uint32_t a;
    asm("{ .reg .u64 t; cvta.to.shared.u64 t, %1; cvt.u32.u64 %0, t; }" : "=r"(a) : "l"(p));
    return a;
}
__device__ __forceinline__ void ldm_x4(uint32_t* r, uint32_t addr) {
    asm volatile("ldmatrix.sync.aligned.m8n8.x4.shared.b16 {%0,%1,%2,%3}, [%4];"
                 : "=r"(r[0]), "=r"(r[1]), "=r"(r[2]), "=r"(r[3]) : "r"(addr));
}
__device__ __forceinline__ void ldm_x4_t(uint32_t* r, uint32_t addr) {
    asm volatile("ldmatrix.sync.aligned.m8n8.x4.trans.shared.b16 {%0,%1,%2,%3}, [%4];"
                 : "=r"(r[0]), "=r"(r[1]), "=r"(r[2]), "=r"(r[3]) : "r"(addr));
}
__device__ __forceinline__ void mma16816(float* d, const uint32_t* a, const uint32_t* b) {
    asm volatile(
        "mma.sync.aligned.m16n8k16.row.col.f32.bf16.bf16.f32 "
        "{%0,%1,%2,%3}, {%4,%5,%6,%7}, {%8,%9}, {%0,%1,%2,%3};"
        : "+f"(d[0]), "+f"(d[1]), "+f"(d[2]), "+f"(d[3])
        : "r"(a[0]), "r"(a[1]), "r"(a[2]), "r"(a[3]), "r"(b[0]), "r"(b[1]));
}

// 8 k16-steps of the 128x128x128 3-term split GEMM for one warp
__device__ __forceinline__ void gemm_chunk(uint32_t Ah, uint32_t Al,
                                           uint32_t Wh, uint32_t Wl,
                                           float acc[2][8][4],
                                           int wm, int wn, int lane)
{
    const int lr = lane & 15;        // row within 16
    const int lc = (lane >> 4) * 8;  // 8-col group
#pragma unroll 1
    for (int kk = 0; kk < 8; ++kk) {
        uint32_t ah[2][4], al[2][4];
#pragma unroll
        for (int t = 0; t < 2; ++t) {
            uint32_t ao = ((wm * 32 + t * 16 + lr) * RS + kk * 16 + lc) * 2;
            ldm_x4(ah[t], Ah + ao);
            ldm_x4(al[t], Al + ao);
        }
        uint32_t bh[4][4], bl[4][4];
#pragma unroll
        for (int g = 0; g < 4; ++g) {
            uint32_t bo = ((kk * 16 + lr) * RS + wn * 64 + g * 16 + lc) * 2;
            ldm_x4_t(bh[g], Wh + bo);
            ldm_x4_t(bl[g], Wl + bo);
        }
#pragma unroll
        for (int t = 0; t < 2; ++t)
#pragma unroll
            for (int g = 0; g < 4; ++g) {
                mma16816(acc[t][2 * g],     ah[t], &bh[g][0]);
                mma16816(acc[t][2 * g + 1], ah[t], &bh[g][2]);
                mma16816(acc[t][2 * g],     al[t], &bh[g][0]);
                mma16816(acc[t][2 * g + 1], al[t], &bh[g][2]);
                mma16816(acc[t][2 * g],     ah[t], &bl[g][0]);
                mma16816(acc[t][2 * g + 1], ah[t], &bl[g][2]);
            }
    }
}

// ---------------- weight prep: hi/lo bf16 split (row-major, no transpose) ----------------
__global__ void prep_kernel(const float* __restrict__ W1, const float* __restrict__ W2) {
    int i = blockIdx.x * blockDim.x + threadIdx.x;
    if (i < 384 * 128) {
        float v = W1[i];
        __nv_bfloat16 h = __float2bfloat16(v);
        g_W1_hi[i] = h;
        g_W1_lo[i] = __float2bfloat16(v - __bfloat162float(h));
    }
    if (i < 128 * 128) {
        float v = W2[i];
        __nv_bfloat16 h = __float2bfloat16(v);
        g_W2_hi[i] = h;
        g_W2_lo[i] = __float2bfloat16(v - __bfloat162float(h));
    }
}

// ---------------- main fused kernel ----------------
__global__ void __launch_bounds__(THREADS, 1)
edgeblock_mma(const float* __restrict__ cell,
              const float* __restrict__ edge,
              const float* __restrict__ b1,
              const float* __restrict__ b2,
              const int*   __restrict__ eidx,
              float* __restrict__ out,
              int E)
{
    extern __shared__ __align__(128) __nv_bfloat16 sm[];
    __nv_bfloat16* Ah = sm;
    __nv_bfloat16* Al = sm + TILE_ELEMS;
    __nv_bfloat16* Wh = sm + 2 * TILE_ELEMS;
    __nv_bfloat16* Wl = sm + 3 * TILE_ELEMS;
    const uint32_t sb   = smem_u32(sm);
    const uint32_t Ah_u = sb;
    const uint32_t Al_u = sb + TILE_BYTES;
    const uint32_t Wh_u = sb + 2 * TILE_BYTES;
    const uint32_t Wl_u = sb + 3 * TILE_BYTES;

    const int tid = threadIdx.x, wid = tid >> 5, lane = tid & 31;
    const int wm = wid >> 1, wn = wid & 1;
    const int e0 = blockIdx.x * TILE_M;

    float acc[2][8][4];
#pragma unroll
    for (int t = 0; t < 2; ++t)
#pragma unroll
        for (int j = 0; j < 8; ++j)
#pragma unroll
            for (int c = 0; c < 4; ++c) acc[t][j][c] = 0.0f;

    // ===== GEMM1: 3 K-chunks of 128 (src-gather, dst-gather, edge rows) =====
#pragma unroll 1
    for (int ch = 0; ch < 3; ++ch) {
        // gather + hi/lo split A chunk: idx = row*32 + c4 (float4 col)
#pragma unroll 1
        for (int i = 0; i < 16; ++i) {
            int idx = i * 256 + tid;
            int row = idx >> 5, c4 = idx & 31;
            int e = e0 + row; int eL = (e < E) ? e : (E - 1);
            const float* base;
            if (ch == 0)      base = cell + (size_t)eidx[eL] * 128;
            else if (ch == 1) base = cell + (size_t)eidx[E + eL] * 128;
            else              base = edge + (size_t)eL * 128;
            float4 v = reinterpret_cast<const float4*>(base)[c4];
            __nv_bfloat162 h0 = __float22bfloat162_rn(make_float2(v.x, v.y));
            __nv_bfloat162 h1 = __float22bfloat162_rn(make_float2(v.z, v.w));
            __nv_bfloat162 l0 = __float22bfloat162_rn(make_float2(
                v.x - __bfloat162float(h0.x), v.y - __bfloat162float(h0.y)));
            __nv_bfloat162 l1 = __float22bfloat162_rn(make_float2(
                v.z - __bfloat162float(h1.x), v.w - __bfloat162float(h1.y)));
            uint64_t hh = ((uint64_t)*reinterpret_cast<uint32_t*>(&h1) << 32) |
                           *reinterpret_cast<uint32_t*>(&h0);
            uint64_t ll = ((uint64_t)*reinterpret_cast<uint32_t*>(&l1) << 32) |
                           *reinterpret_cast<uint32_t*>(&l0);
            int off = row * RS + c4 * 4;   // 8B aligned (RS even, c4*4 mult of 4)
            *reinterpret_cast<uint64_t*>(Ah + off) = hh;
            *reinterpret_cast<uint64_t*>(Al + off) = ll;
        }
        // stage W1 chunk [128k x 128n] hi/lo: idx = row*64 + c2 (u32 col)
        {
            const uint32_t* wh = reinterpret_cast<const uint32_t*>(g_W1_hi + (size_t)ch * 128 * 128);
            const uint32_t* wl = reinterpret_cast<const uint32_t*>(g_W1_lo + (size_t)ch * 128 * 128);
#pragma unroll
            for (int i = 0; i < 32; ++i) {
                int idx = i * 256 + tid;
                int row = idx >> 6, c2 = idx & 63;
                int off = row * RS + c2 * 2;
                *reinterpret_cast<uint32_t*>(Wh + off) = wh[idx];
                *reinterpret_cast<uint32_t*>(Wl + off) = wl[idx];
            }
        }
        __syncthreads();
        gemm_chunk(Ah_u, Al_u, Wh_u, Wl_u, acc, wm, wn, lane);
        __syncthreads();   // compute done before next chunk overwrites tiles
    }

    // ===== epilogue1: h = relu(acc + b1), split hi/lo back into A tiles; stage W2 =====
    {
        const int colb = wn * 64 + (lane & 3) * 2;
        const int rowb = wm * 32 + (lane >> 2);
#pragma unroll
        for (int t = 0; t < 2; ++t)
#pragma unroll
            for (int j = 0; j < 8; ++j) {
                int col = colb + j * 8;
                float bx = __ldg(&b1[col]), by = __ldg(&b1[col + 1]);
#pragma unroll
                for (int half = 0; half < 2; ++half) {
                    int row = rowb + t * 16 + half * 8;
                    float x = fmaxf(acc[t][j][2 * half]     + bx, 0.0f);
                    float y = fmaxf(acc[t][j][2 * half + 1] + by, 0.0f);
                    __nv_bfloat162 h2 = __float22bfloat162_rn(make_float2(x, y));
                    __nv_bfloat162 l2 = __float22bfloat162_rn(make_float2(
                        x - __bfloat162float(h2.x), y - __bfloat162float(h2.y)));
                    int off = row * RS + col;
                    *reinterpret_cast<uint32_t*>(Ah + off) = *reinterpret_cast<uint32_t*>(&h2);
                    *reinterpret_cast<uint32_t*>(Al + off) = *reinterpret_cast<uint32_t*>(&l2);
                }
            }
        // stage W2 hi/lo
        const uint32_t* wh = reinterpret_cast<const uint32_t*>(g_W2_hi);
        const uint32_t* wl = reinterpret_cast<const uint32_t*>(g_W2_lo);
#pragma unroll
        for (int i = 0; i < 32; ++i) {
            int idx = i * 256 + tid;
            int row = idx >> 6, c2 = idx & 63;
            int off = row * RS + c2 * 2;
            *reinterpret_cast<uint32_t*>(Wh + off) = wh[idx];
            *reinterpret_cast<uint32_t*>(Wl + off) = wl[idx];
        }
        // zero accumulators for GEMM2
#pragma unroll
        for (int t = 0; t < 2; ++t)
#pragma unroll
            for (int j = 0; j < 8; ++j)
#pragma unroll
                for (int c = 0; c < 4; ++c) acc[t][j][c] = 0.0f;
    }
    __syncthreads();

    // ===== GEMM2: [128 x 128] @ W2 =====
    gemm_chunk(Ah_u, Al_u, Wh_u, Wl_u, acc, wm, wn, lane);

    // ===== epilogue2: + b2, store =====
    {
        const int colb = wn * 64 + (lane & 3) * 2;
        const int rowb = wm * 32 + (lane >> 2);
#pragma unroll
        for (int t = 0; t < 2; ++t)
#pragma unroll
            for (int j = 0; j < 8; ++j) {
                int col = colb + j * 8;
                float bx = __ldg(&b2[col]), by = __ldg(&b2[col + 1]);
#pragma unroll
                for (int half = 0; half < 2; ++half) {
                    int row = rowb + t * 16 + half * 8;
                    int e = e0 + row;
                    if (e < E) {
                        float2 o = make_float2(acc[t][j][2 * half] + bx,
                                               acc[t][j][2 * half + 1] + by);
                        *reinterpret_cast<float2*>(out + (size_t)e * 128 + col) = o;
                    }
                }
            }
    }
}

extern "C" void kernel_launch(void* const* d_in, const int* in_sizes, int n_in,
                              void* d_out, int out_size) {
    const float* cell = (const float*)d_in[0];   // [50000,128]
    const float* edge = (const float*)d_in[1];   // [E,128]
    const float* W1   = (const float*)d_in[2];   // [384,128]
    const float* b1   = (const float*)d_in[3];   // [128]
    const float* W2   = (const float*)d_in[4];   // [128,128]
    const float* b2   = (const float*)d_in[5];   // [128]
    const int*   eidx = (const int*)d_in[6];     // [2,E]
    float* out = (float*)d_out;

    int E = in_sizes[6] / 2;

    prep_kernel<<<(384 * 128 + 255) / 256, 256>>>(W1, W2);

    cudaFuncSetAttribute(edgeblock_mma,
                         cudaFuncAttributeMaxDynamicSharedMemorySize, SMEM_BYTES);
    int grid = (E + TILE_M - 1) / TILE_M;
    edgeblock_mma<<<grid, THREADS, SMEM_BYTES>>>(cell, edge, b1, b2, eidx, out, E);
}

// round 6
// speedup vs baseline: 2.9106x; 1.4462x over previous
#include <cuda_runtime.h>
#include <cuda_bf16.h>
#include <cstdint>

// EdgeBlock: out = relu(concat(cell[src],cell[dst],edge) @ W1 + b1) @ W2 + b2
// bf16 3-term split (hi*hi + lo*hi + hi*lo) on mma.sync.m16n8k16, fp32 accum.
// v2: TILE_M=64, smem 104KB -> 2 CTAs/SM, cp.async weight staging.

#define THREADS 256
#define TILE_M  64
#define RS      136                     // bf16 per smem row (128 + 8 pad)
#define A_ELEMS (64 * RS)
#define W_ELEMS (128 * RS)
#define A_BYTES (A_ELEMS * 2)           // 17408
#define W_BYTES (W_ELEMS * 2)           // 34816
#define SMEM_BYTES (2 * A_BYTES + 2 * W_BYTES)   // 104448

// pre-split weights, row-major k x n
__device__ __nv_bfloat16 g_W1_hi[384 * 128];
__device__ __nv_bfloat16 g_W1_lo[384 * 128];
__device__ __nv_bfloat16 g_W2_hi[128 * 128];
__device__ __nv_bfloat16 g_W2_lo[128 * 128];

// ---------------- helpers ----------------
__device__ __forceinline__ uint32_t smem_u32(const void* p) {
    uint32_t a;
    asm("{ .reg .u64 t; cvta.to.shared.u64 t, %1; cvt.u32.u64 %0, t; }" : "=r"(a) : "l"(p));
    return a;
}
__device__ __forceinline__ void ldm_x4(uint32_t* r, uint32_t addr) {
    asm volatile("ldmatrix.sync.aligned.m8n8.x4.shared.b16 {%0,%1,%2,%3}, [%4];"
                 : "=r"(r[0]), "=r"(r[1]), "=r"(r[2]), "=r"(r[3]) : "r"(addr));
}
__device__ __forceinline__ void ldm_x4_t(uint32_t* r, uint32_t addr) {
    asm volatile("ldmatrix.sync.aligned.m8n8.x4.trans.shared.b16 {%0,%1,%2,%3}, [%4];"
                 : "=r"(r[0]), "=r"(r[1]), "=r"(r[2]), "=r"(r[3]) : "r"(addr));
}
__device__ __forceinline__ void mma16816(float* d, const uint32_t* a, const uint32_t* b) {
    asm volatile(
        "mma.sync.aligned.m16n8k16.row.col.f32.bf16.bf16.f32 "
        "{%0,%1,%2,%3}, {%4,%5,%6,%7}, {%8,%9}, {%0,%1,%2,%3};"
        : "+f"(d[0]), "+f"(d[1]), "+f"(d[2]), "+f"(d[3])
        : "r"(a[0]), "r"(a[1]), "r"(a[2]), "r"(a[3]), "r"(b[0]), "r"(b[1]));
}
__device__ __forceinline__ void cp16(uint32_t dst, const void* src) {
    asm volatile("cp.async.cg.shared.global [%0], [%1], 16;" :: "r"(dst), "l"(src));
}
#define CP_COMMIT() asm volatile("cp.async.commit_group;" ::: "memory")
#define CP_WAIT0()  asm volatile("cp.async.wait_group 0;" ::: "memory")

// one warp's share of a 64x128x128 chunk, 3-term split
__device__ __forceinline__ void gemm_chunk(uint32_t Ah, uint32_t Al,
                                           uint32_t Wh, uint32_t Wl,
                                           float acc[2][4][4],
                                           int wm, int wn, int lane)
{
    const int lr = lane & 15;
    const int lc = (lane >> 4) * 8;
#pragma unroll 1
    for (int kk = 0; kk < 8; ++kk) {
        uint32_t ah[2][4], al[2][4];
#pragma unroll
        for (int t = 0; t < 2; ++t) {
            uint32_t ao = ((wm * 32 + t * 16 + lr) * RS + kk * 16 + lc) * 2;
            ldm_x4(ah[t], Ah + ao);
            ldm_x4(al[t], Al + ao);
        }
        uint32_t bh[2][4], bl[2][4];
#pragma unroll
        for (int g = 0; g < 2; ++g) {
            uint32_t bo = ((kk * 16 + lr) * RS + wn * 32 + g * 16 + lc) * 2;
            ldm_x4_t(bh[g], Wh + bo);
            ldm_x4_t(bl[g], Wl + bo);
        }
#pragma unroll
        for (int t = 0; t < 2; ++t)
#pragma unroll
            for (int g = 0; g < 2; ++g) {
                mma16816(acc[t][2 * g],     ah[t], &bh[g][0]);
                mma16816(acc[t][2 * g + 1], ah[t], &bh[g][2]);
                mma16816(acc[t][2 * g],     al[t], &bh[g][0]);
                mma16816(acc[t][2 * g + 1], al[t], &bh[g][2]);
                mma16816(acc[t][2 * g],     ah[t], &bl[g][0]);
                mma16816(acc[t][2 * g + 1], ah[t], &bl[g][2]);
            }
    }
}

// stage one 128x128 bf16 tile pair (hi/lo) via cp.async
__device__ __forceinline__ void stage_w(uint32_t Wh, uint32_t Wl,
                                        const __nv_bfloat16* wh,
                                        const __nv_bfloat16* wl, int tid)
{
#pragma unroll
    for (int i = 0; i < 8; ++i) {
        int idx = i * 256 + tid;          // 2048 16B-groups
        int row = idx >> 4, c8 = idx & 15;
        uint32_t off = (row * RS + c8 * 8) * 2;
        cp16(Wh + off, wh + row * 128 + c8 * 8);
        cp16(Wl + off, wl + row * 128 + c8 * 8);
    }
}

// ---------------- weight prep ----------------
__global__ void prep_kernel(const float* __restrict__ W1, const float* __restrict__ W2) {
    int i = blockIdx.x * blockDim.x + threadIdx.x;
    if (i < 384 * 128) {
        float v = W1[i];
        __nv_bfloat16 h = __float2bfloat16(v);
        g_W1_hi[i] = h;
        g_W1_lo[i] = __float2bfloat16(v - __bfloat162float(h));
    }
    if (i < 128 * 128) {
        float v = W2[i];
        __nv_bfloat16 h = __float2bfloat16(v);
        g_W2_hi[i] = h;
        g_W2_lo[i] = __float2bfloat16(v - __bfloat162float(h));
    }
}

// ---------------- main fused kernel ----------------
__global__ void __launch_bounds__(THREADS, 2)
edgeblock_mma(const float* __restrict__ cell,
              const float* __restrict__ edge,
              const float* __restrict__ b1,
              const float* __restrict__ b2,
              const int*   __restrict__ eidx,
              float* __restrict__ out,
              int E)
{
    extern __shared__ __align__(128) __nv_bfloat16 sm[];
    __nv_bfloat16* Ah = sm;
    __nv_bfloat16* Al = sm + A_ELEMS;
    const uint32_t sb   = smem_u32(sm);
    const uint32_t Ah_u = sb;
    const uint32_t Al_u = sb + A_BYTES;
    const uint32_t Wh_u = sb + 2 * A_BYTES;
    const uint32_t Wl_u = sb + 2 * A_BYTES + W_BYTES;

    const int tid = threadIdx.x, wid = tid >> 5, lane = tid & 31;
    const int wm = wid & 1, wn = wid >> 1;      // 2 x 4 warp grid, 32x32 tiles
    const int e0 = blockIdx.x * TILE_M;

    float acc[2][4][4];
#pragma unroll
    for (int t = 0; t < 2; ++t)
#pragma unroll
        for (int j = 0; j < 4; ++j)
#pragma unroll
            for (int c = 0; c < 4; ++c) acc[t][j][c] = 0.0f;

    // ===== GEMM1: 3 K-chunks of 128 =====
#pragma unroll 1
    for (int ch = 0; ch < 3; ++ch) {
        // prefetch W chunk (async) while doing the gather+convert
        stage_w(Wh_u, Wl_u,
                g_W1_hi + (size_t)ch * 128 * 128,
                g_W1_lo + (size_t)ch * 128 * 128, tid);
        CP_COMMIT();

        // gather + hi/lo split A chunk: 64 rows x 32 float4 cols
#pragma unroll 1
        for (int i = 0; i < 8; ++i) {
            int idx = i * 256 + tid;
            int row = idx >> 5, c4 = idx & 31;
            int e = e0 + row; int eL = (e < E) ? e : (E - 1);
            const float* base;
            if (ch == 0)      base = cell + (size_t)eidx[eL] * 128;
            else if (ch == 1) base = cell + (size_t)eidx[E + eL] * 128;
            else              base = edge + (size_t)eL * 128;
            float4 v = reinterpret_cast<const float4*>(base)[c4];
            __nv_bfloat162 h0 = __float22bfloat162_rn(make_float2(v.x, v.y));
            __nv_bfloat162 h1 = __float22bfloat162_rn(make_float2(v.z, v.w));
            __nv_bfloat162 l0 = __float22bfloat162_rn(make_float2(
                v.x - __bfloat162float(h0.x), v.y - __bfloat162float(h0.y)));
            __nv_bfloat162 l1 = __float22bfloat162_rn(make_float2(
                v.z - __bfloat162float(h1.x), v.w - __bfloat162float(h1.y)));
            uint64_t hh = ((uint64_t)*reinterpret_cast<uint32_t*>(&h1) << 32) |
                           *reinterpret_cast<uint32_t*>(&h0);
            uint64_t ll = ((uint64_t)*reinterpret_cast<uint32_t*>(&l1) << 32) |
                           *reinterpret_cast<uint32_t*>(&l0);
            int off = row * RS + c4 * 4;
            *reinterpret_cast<uint64_t*>(Ah + off) = hh;
            *reinterpret_cast<uint64_t*>(Al + off) = ll;
        }
        CP_WAIT0();
        __syncthreads();
        gemm_chunk(Ah_u, Al_u, Wh_u, Wl_u, acc, wm, wn, lane);
        __syncthreads();
    }

    // ===== epilogue1: h = relu(acc+b1) split -> A tiles; prefetch W2 =====
    stage_w(Wh_u, Wl_u, g_W2_hi, g_W2_lo, tid);
    CP_COMMIT();
    {
        const int colb = wn * 32 + (lane & 3) * 2;
        const int rowb = wm * 32 + (lane >> 2);
#pragma unroll
        for (int t = 0; t < 2; ++t)
#pragma unroll
            for (int j = 0; j < 4; ++j) {
                int col = colb + j * 8;
                float bx = __ldg(&b1[col]), by = __ldg(&b1[col + 1]);
#pragma unroll
                for (int half = 0; half < 2; ++half) {
                    int row = rowb + t * 16 + half * 8;
                    float x = fmaxf(acc[t][j][2 * half]     + bx, 0.0f);
                    float y = fmaxf(acc[t][j][2 * half + 1] + by, 0.0f);
                    __nv_bfloat162 h2 = __float22bfloat162_rn(make_float2(x, y));
                    __nv_bfloat162 l2 = __float22bfloat162_rn(make_float2(
                        x - __bfloat162float(h2.x), y - __bfloat162float(h2.y)));
                    int off = row * RS + col;
                    *reinterpret_cast<uint32_t*>(Ah + off) = *reinterpret_cast<uint32_t*>(&h2);
                    *reinterpret_cast<uint32_t*>(Al + off) = *reinterpret_cast<uint32_t*>(&l2);
                }
            }
#pragma unroll
        for (int t = 0; t < 2; ++t)
#pragma unroll
            for (int j = 0; j < 4; ++j)
#pragma unroll
                for (int c = 0; c < 4; ++c) acc[t][j][c] = 0.0f;
    }
    CP_WAIT0();
    __syncthreads();

    // ===== GEMM2 =====
    gemm_chunk(Ah_u, Al_u, Wh_u, Wl_u, acc, wm, wn, lane);

    // ===== epilogue2: + b2, store =====
    {
        const int colb = wn * 32 + (lane & 3) * 2;
        const int rowb = wm * 32 + (lane >> 2);
#pragma unroll
        for (int t = 0; t < 2; ++t)
#pragma unroll
            for (int j = 0; j < 4; ++j) {
                int col = colb + j * 8;
                float bx = __ldg(&b2[col]), by = __ldg(&b2[col + 1]);
#pragma unroll
                for (int half = 0; half < 2; ++half) {
                    int row = rowb + t * 16 + half * 8;
                    int e = e0 + row;
                    if (e < E) {
                        float2 o = make_float2(acc[t][j][2 * half] + bx,
                                               acc[t][j][2 * half + 1] + by);
                        *reinterpret_cast<float2*>(out + (size_t)e * 128 + col) = o;
                    }
                }
            }
    }
}

extern "C" void kernel_launch(void* const* d_in, const int* in_sizes, int n_in,
                              void* d_out, int out_size) {
    const float* cell = (const float*)d_in[0];   // [50000,128]
    const float* edge = (const float*)d_in[1];   // [E,128]
    const float* W1   = (const float*)d_in[2];   // [384,128]
    const float* b1   = (const float*)d_in[3];   // [128]
    const float* W2   = (const float*)d_in[4];   // [128,128]
    const float* b2   = (const float*)d_in[5];   // [128]
    const int*   eidx = (const int*)d_in[6];     // [2,E]
    float* out = (float*)d_out;

    int E = in_sizes[6] / 2;

    prep_kernel<<<(384 * 128 + 255) / 256, 256>>>(W1, W2);

    cudaFuncSetAttribute(edgeblock_mma,
                         cudaFuncAttributeMaxDynamicSharedMemorySize, SMEM_BYTES);
    int grid = (E + TILE_M - 1) / TILE_M;
    edgeblock_mma<<<grid, THREADS, SMEM_BYTES>>>(cell, edge, b1, b2, eidx, out, E);
}

// round 7
// speedup vs baseline: 2.9125x; 1.0006x over previous
#include <cuda_runtime.h>
#include <cuda_bf16.h>
#include <cstdint>

// EdgeBlock: out = relu(concat(cell[src],cell[dst],edge) @ W1 + b1) @ W2 + b2
// bf16 3-term split (hi*hi + lo*hi + hi*lo) on mma.sync.m16n8k16, fp32 accum.
// v2: TILE_M=64, smem 104KB -> 2 CTAs/SM, cp.async weight staging.

#define THREADS 256
#define TILE_M  64
#define RS      136                     // bf16 per smem row (128 + 8 pad)
#define A_ELEMS (64 * RS)
#define W_ELEMS (128 * RS)
#define A_BYTES (A_ELEMS * 2)           // 17408
#define W_BYTES (W_ELEMS * 2)           // 34816
#define SMEM_BYTES (2 * A_BYTES + 2 * W_BYTES)   // 104448

// pre-split weights, row-major k x n
__device__ __nv_bfloat16 g_W1_hi[384 * 128];
__device__ __nv_bfloat16 g_W1_lo[384 * 128];
__device__ __nv_bfloat16 g_W2_hi[128 * 128];
__device__ __nv_bfloat16 g_W2_lo[128 * 128];

// ---------------- helpers ----------------
__device__ __forceinline__ uint32_t smem_u32(const void* p) {
    uint32_t a;
    asm("{ .reg .u64 t; cvta.to.shared.u64 t, %1; cvt.u32.u64 %0, t; }" : "=r"(a) : "l"(p));
    return a;
}
__device__ __forceinline__ void ldm_x4(uint32_t* r, uint32_t addr) {
    asm volatile("ldmatrix.sync.aligned.m8n8.x4.shared.b16 {%0,%1,%2,%3}, [%4];"
                 : "=r"(r[0]), "=r"(r[1]), "=r"(r[2]), "=r"(r[3]) : "r"(addr));
}
__device__ __forceinline__ void ldm_x4_t(uint32_t* r, uint32_t addr) {
    asm volatile("ldmatrix.sync.aligned.m8n8.x4.trans.shared.b16 {%0,%1,%2,%3}, [%4];"
                 : "=r"(r[0]), "=r"(r[1]), "=r"(r[2]), "=r"(r[3]) : "r"(addr));
}
__device__ __forceinline__ void mma16816(float* d, const uint32_t* a, const uint32_t* b) {
    asm volatile(
        "mma.sync.aligned.m16n8k16.row.col.f32.bf16.bf16.f32 "
        "{%0,%1,%2,%3}, {%4,%5,%6,%7}, {%8,%9}, {%0,%1,%2,%3};"
        : "+f"(d[0]), "+f"(d[1]), "+f"(d[2]), "+f"(d[3])
        : "r"(a[0]), "r"(a[1]), "r"(a[2]), "r"(a[3]), "r"(b[0]), "r"(b[1]));
}
__device__ __forceinline__ void cp16(uint32_t dst, const void* src) {
    asm volatile("cp.async.cg.shared.global [%0], [%1], 16;" :: "r"(dst), "l"(src));
}
#define CP_COMMIT() asm volatile("cp.async.commit_group;" ::: "memory")
#define CP_WAIT0()  asm volatile("cp.async.wait_group 0;" ::: "memory")

// one warp's share of a 64x128x128 chunk, 3-term split
__device__ __forceinline__ void gemm_chunk(uint32_t Ah, uint32_t Al,
                                           uint32_t Wh, uint32_t Wl,
                                           float acc[2][4][4],
                                           int wm, int wn, int lane)
{
    const int lr = lane & 15;
    const int lc = (lane >> 4) * 8;
#pragma unroll 1
    for (int kk = 0; kk < 8; ++kk) {
        uint32_t ah[2][4], al[2][4];
#pragma unroll
        for (int t = 0; t < 2; ++t) {
            uint32_t ao = ((wm * 32 + t * 16 + lr) * RS + kk * 16 + lc) * 2;
            ldm_x4(ah[t], Ah + ao);
            ldm_x4(al[t], Al + ao);
        }
        uint32_t bh[2][4], bl[2][4];
#pragma unroll
        for (int g = 0; g < 2; ++g) {
            uint32_t bo = ((kk * 16 + lr) * RS + wn * 32 + g * 16 + lc) * 2;
            ldm_x4_t(bh[g], Wh + bo);
            ldm_x4_t(bl[g], Wl + bo);
        }
#pragma unroll
        for (int t = 0; t < 2; ++t)
#pragma unroll
            for (int g = 0; g < 2; ++g) {
                mma16816(acc[t][2 * g],     ah[t], &bh[g][0]);
                mma16816(acc[t][2 * g + 1], ah[t], &bh[g][2]);
                mma16816(acc[t][2 * g],     al[t], &bh[g][0]);
                mma16816(acc[t][2 * g + 1], al[t], &bh[g][2]);
                mma16816(acc[t][2 * g],     ah[t], &bl[g][0]);
                mma16816(acc[t][2 * g + 1], ah[t], &bl[g][2]);
            }
    }
}

// stage one 128x128 bf16 tile pair (hi/lo) via cp.async
__device__ __forceinline__ void stage_w(uint32_t Wh, uint32_t Wl,
                                        const __nv_bfloat16* wh,
                                        const __nv_bfloat16* wl, int tid)
{
#pragma unroll
    for (int i = 0; i < 8; ++i) {
        int idx = i * 256 + tid;          // 2048 16B-groups
        int row = idx >> 4, c8 = idx & 15;
        uint32_t off = (row * RS + c8 * 8) * 2;
        cp16(Wh + off, wh + row * 128 + c8 * 8);
        cp16(Wl + off, wl + row * 128 + c8 * 8);
    }
}

// ---------------- weight prep ----------------
__global__ void prep_kernel(const float* __restrict__ W1, const float* __restrict__ W2) {
    int i = blockIdx.x * blockDim.x + threadIdx.x;
    if (i < 384 * 128) {
        float v = W1[i];
        __nv_bfloat16 h = __float2bfloat16(v);
        g_W1_hi[i] = h;
        g_W1_lo[i] = __float2bfloat16(v - __bfloat162float(h));
    }
    if (i < 128 * 128) {
        float v = W2[i];
        __nv_bfloat16 h = __float2bfloat16(v);
        g_W2_hi[i] = h;
        g_W2_lo[i] = __float2bfloat16(v - __bfloat162float(h));
    }
}

// ---------------- main fused kernel ----------------
__global__ void __launch_bounds__(THREADS, 2)
edgeblock_mma(const float* __restrict__ cell,
              const float* __restrict__ edge,
              const float* __restrict__ b1,
              const float* __restrict__ b2,
              const int*   __restrict__ eidx,
              float* __restrict__ out,
              int E)
{
    extern __shared__ __align__(128) __nv_bfloat16 sm[];
    __nv_bfloat16* Ah = sm;
    __nv_bfloat16* Al = sm + A_ELEMS;
    const uint32_t sb   = smem_u32(sm);
    const uint32_t Ah_u = sb;
    const uint32_t Al_u = sb + A_BYTES;
    const uint32_t Wh_u = sb + 2 * A_BYTES;
    const uint32_t Wl_u = sb + 2 * A_BYTES + W_BYTES;

    const int tid = threadIdx.x, wid = tid >> 5, lane = tid & 31;
    const int wm = wid & 1, wn = wid >> 1;      // 2 x 4 warp grid, 32x32 tiles
    const int e0 = blockIdx.x * TILE_M;

    float acc[2][4][4];
#pragma unroll
    for (int t = 0; t < 2; ++t)
#pragma unroll
        for (int j = 0; j < 4; ++j)
#pragma unroll
            for (int c = 0; c < 4; ++c) acc[t][j][c] = 0.0f;

    // ===== GEMM1: 3 K-chunks of 128 =====
#pragma unroll 1
    for (int ch = 0; ch < 3; ++ch) {
        // prefetch W chunk (async) while doing the gather+convert
        stage_w(Wh_u, Wl_u,
                g_W1_hi + (size_t)ch * 128 * 128,
                g_W1_lo + (size_t)ch * 128 * 128, tid);
        CP_COMMIT();

        // gather + hi/lo split A chunk: 64 rows x 32 float4 cols
#pragma unroll 1
        for (int i = 0; i < 8; ++i) {
            int idx = i * 256 + tid;
            int row = idx >> 5, c4 = idx & 31;
            int e = e0 + row; int eL = (e < E) ? e : (E - 1);
            const float* base;
            if (ch == 0)      base = cell + (size_t)eidx[eL] * 128;
            else if (ch == 1) base = cell + (size_t)eidx[E + eL] * 128;
            else              base = edge + (size_t)eL * 128;
            float4 v = reinterpret_cast<const float4*>(base)[c4];
            __nv_bfloat162 h0 = __float22bfloat162_rn(make_float2(v.x, v.y));
            __nv_bfloat162 h1 = __float22bfloat162_rn(make_float2(v.z, v.w));
            __nv_bfloat162 l0 = __float22bfloat162_rn(make_float2(
                v.x - __bfloat162float(h0.x), v.y - __bfloat162float(h0.y)));
            __nv_bfloat162 l1 = __float22bfloat162_rn(make_float2(
                v.z - __bfloat162float(h1.x), v.w - __bfloat162float(h1.y)));
            uint64_t hh = ((uint64_t)*reinterpret_cast<uint32_t*>(&h1) << 32) |
                           *reinterpret_cast<uint32_t*>(&h0);
            uint64_t ll = ((uint64_t)*reinterpret_cast<uint32_t*>(&l1) << 32) |
                           *reinterpret_cast<uint32_t*>(&l0);
            int off = row * RS + c4 * 4;
            *reinterpret_cast<uint64_t*>(Ah + off) = hh;
            *reinterpret_cast<uint64_t*>(Al + off) = ll;
        }
        CP_WAIT0();
        __syncthreads();
        gemm_chunk(Ah_u, Al_u, Wh_u, Wl_u, acc, wm, wn, lane);
        __syncthreads();
    }

    // ===== epilogue1: h = relu(acc+b1) split -> A tiles; prefetch W2 =====
    stage_w(Wh_u, Wl_u, g_W2_hi, g_W2_lo, tid);
    CP_COMMIT();
    {
        const int colb = wn * 32 + (lane & 3) * 2;
        const int rowb = wm * 32 + (lane >> 2);
#pragma unroll
        for (int t = 0; t < 2; ++t)
#pragma unroll
            for (int j = 0; j < 4; ++j) {
                int col = colb + j * 8;
                float bx = __ldg(&b1[col]), by = __ldg(&b1[col + 1]);
#pragma unroll
                for (int half = 0; half < 2; ++half) {
                    int row = rowb + t * 16 + half * 8;
                    float x = fmaxf(acc[t][j][2 * half]     + bx, 0.0f);
                    float y = fmaxf(acc[t][j][2 * half + 1] + by, 0.0f);
                    __nv_bfloat162 h2 = __float22bfloat162_rn(make_float2(x, y));
                    __nv_bfloat162 l2 = __float22bfloat162_rn(make_float2(
                        x - __bfloat162float(h2.x), y - __bfloat162float(h2.y)));
                    int off = row * RS + col;
                    *reinterpret_cast<uint32_t*>(Ah + off) = *reinterpret_cast<uint32_t*>(&h2);
                    *reinterpret_cast<uint32_t*>(Al + off) = *reinterpret_cast<uint32_t*>(&l2);
                }
            }
#pragma unroll
        for (int t = 0; t < 2; ++t)
#pragma unroll
            for (int j = 0; j < 4; ++j)
#pragma unroll
                for (int c = 0; c < 4; ++c) acc[t][j][c] = 0.0f;
    }
    CP_WAIT0();
    __syncthreads();

    // ===== GEMM2 =====
    gemm_chunk(Ah_u, Al_u, Wh_u, Wl_u, acc, wm, wn, lane);

    // ===== epilogue2: + b2, store =====
    {
        const int colb = wn * 32 + (lane & 3) * 2;
        const int rowb = wm * 32 + (lane >> 2);
#pragma unroll
        for (int t = 0; t < 2; ++t)
#pragma unroll
            for (int j = 0; j < 4; ++j) {
                int col = colb + j * 8;
                float bx = __ldg(&b2[col]), by = __ldg(&b2[col + 1]);
#pragma unroll
                for (int half = 0; half < 2; ++half) {
                    int row = rowb + t * 16 + half * 8;
                    int e = e0 + row;
                    if (e < E) {
                        float2 o = make_float2(acc[t][j][2 * half] + bx,
                                               acc[t][j][2 * half + 1] + by);
                        *reinterpret_cast<float2*>(out + (size_t)e * 128 + col) = o;
                    }
                }
            }
    }
}

extern "C" void kernel_launch(void* const* d_in, const int* in_sizes, int n_in,
                              void* d_out, int out_size) {
    const float* cell = (const float*)d_in[0];   // [50000,128]
    const float* edge = (const float*)d_in[1];   // [E,128]
    const float* W1   = (const float*)d_in[2];   // [384,128]
    const float* b1   = (const float*)d_in[3];   // [128]
    const float* W2   = (const float*)d_in[4];   // [128,128]
    const float* b2   = (const float*)d_in[5];   // [128]
    const int*   eidx = (const int*)d_in[6];     // [2,E]
    float* out = (float*)d_out;

    int E = in_sizes[6] / 2;

    prep_kernel<<<(384 * 128 + 255) / 256, 256>>>(W1, W2);

    cudaFuncSetAttribute(edgeblock_mma,
                         cudaFuncAttributeMaxDynamicSharedMemorySize, SMEM_BYTES);
    int grid = (E + TILE_M - 1) / TILE_M;
    edgeblock_mma<<<grid, THREADS, SMEM_BYTES>>>(cell, edge, b1, b2, eidx, out, E);
}

// round 8
// speedup vs baseline: 3.4015x; 1.1679x over previous
#include <cuda_runtime.h>
#include <cuda_bf16.h>
#include <cstdint>

// EdgeBlock: out = relu(concat(cell[src],cell[dst],edge) @ W1 + b1) @ W2 + b2
// bf16 3-term split (hi*hi + lo*hi + hi*lo) on mma.sync.m16n8k16, fp32 accum.
// v3: TILE_M=64, 2 CTAs/SM, cp.async weights, MLP-8 batched gather,
//     term-major mma ordering + kk unroll for tensor-pipe utilization.

#define THREADS 256
#define TILE_M  64
#define RS      136                     // bf16 per smem row (128 + 8 pad)
#define A_ELEMS (64 * RS)
#define W_ELEMS (128 * RS)
#define A_BYTES (A_ELEMS * 2)           // 17408
#define W_BYTES (W_ELEMS * 2)           // 34816
#define SMEM_BYTES (2 * A_BYTES + 2 * W_BYTES)   // 104448

// pre-split weights, row-major k x n
__device__ __nv_bfloat16 g_W1_hi[384 * 128];
__device__ __nv_bfloat16 g_W1_lo[384 * 128];
__device__ __nv_bfloat16 g_W2_hi[128 * 128];
__device__ __nv_bfloat16 g_W2_lo[128 * 128];

// ---------------- helpers ----------------
__device__ __forceinline__ uint32_t smem_u32(const void* p) {
    uint32_t a;
    asm("{ .reg .u64 t; cvta.to.shared.u64 t, %1; cvt.u32.u64 %0, t; }" : "=r"(a) : "l"(p));
    return a;
}
__device__ __forceinline__ void ldm_x4(uint32_t* r, uint32_t addr) {
    asm volatile("ldmatrix.sync.aligned.m8n8.x4.shared.b16 {%0,%1,%2,%3}, [%4];"
                 : "=r"(r[0]), "=r"(r[1]), "=r"(r[2]), "=r"(r[3]) : "r"(addr));
}
__device__ __forceinline__ void ldm_x4_t(uint32_t* r, uint32_t addr) {
    asm volatile("ldmatrix.sync.aligned.m8n8.x4.trans.shared.b16 {%0,%1,%2,%3}, [%4];"
                 : "=r"(r[0]), "=r"(r[1]), "=r"(r[2]), "=r"(r[3]) : "r"(addr));
}
__device__ __forceinline__ void mma16816(float* d, const uint32_t* a, const uint32_t* b) {
    asm volatile(
        "mma.sync.aligned.m16n8k16.row.col.f32.bf16.bf16.f32 "
        "{%0,%1,%2,%3}, {%4,%5,%6,%7}, {%8,%9}, {%0,%1,%2,%3};"
        : "+f"(d[0]), "+f"(d[1]), "+f"(d[2]), "+f"(d[3])
        : "r"(a[0]), "r"(a[1]), "r"(a[2]), "r"(a[3]), "r"(b[0]), "r"(b[1]));
}
__device__ __forceinline__ void cp16(uint32_t dst, const void* src) {
    asm volatile("cp.async.cg.shared.global [%0], [%1], 16;" :: "r"(dst), "l"(src));
}
#define CP_COMMIT() asm volatile("cp.async.commit_group;" ::: "memory")
#define CP_WAIT0()  asm volatile("cp.async.wait_group 0;" ::: "memory")

// one warp's share of a 64x128x128 chunk, 3-term split, term-major ordering
__device__ __forceinline__ void gemm_chunk(uint32_t Ah, uint32_t Al,
                                           uint32_t Wh, uint32_t Wl,
                                           float acc[2][4][4],
                                           int wm, int wn, int lane)
{
    const int lr = lane & 15;
    const int lc = (lane >> 4) * 8;
#pragma unroll 2
    for (int kk = 0; kk < 8; ++kk) {
        uint32_t ah[2][4], al[2][4];
#pragma unroll
        for (int t = 0; t < 2; ++t) {
            uint32_t ao = ((wm * 32 + t * 16 + lr) * RS + kk * 16 + lc) * 2;
            ldm_x4(ah[t], Ah + ao);
            ldm_x4(al[t], Al + ao);
        }
        uint32_t bh[2][4], bl[2][4];
#pragma unroll
        for (int g = 0; g < 2; ++g) {
            uint32_t bo = ((kk * 16 + lr) * RS + wn * 32 + g * 16 + lc) * 2;
            ldm_x4_t(bh[g], Wh + bo);
            ldm_x4_t(bl[g], Wl + bo);
        }
        // term-major: 8 independent quads per term -> accumulator chains spread out
#pragma unroll
        for (int t = 0; t < 2; ++t)
#pragma unroll
            for (int g = 0; g < 2; ++g) {
                mma16816(acc[t][2 * g],     ah[t], &bh[g][0]);
                mma16816(acc[t][2 * g + 1], ah[t], &bh[g][2]);
            }
#pragma unroll
        for (int t = 0; t < 2; ++t)
#pragma unroll
            for (int g = 0; g < 2; ++g) {
                mma16816(acc[t][2 * g],     al[t], &bh[g][0]);
                mma16816(acc[t][2 * g + 1], al[t], &bh[g][2]);
            }
#pragma unroll
        for (int t = 0; t < 2; ++t)
#pragma unroll
            for (int g = 0; g < 2; ++g) {
                mma16816(acc[t][2 * g],     ah[t], &bl[g][0]);
                mma16816(acc[t][2 * g + 1], ah[t], &bl[g][2]);
            }
    }
}

// stage one 128x128 bf16 tile pair (hi/lo) via cp.async
__device__ __forceinline__ void stage_w(uint32_t Wh, uint32_t Wl,
                                        const __nv_bfloat16* wh,
                                        const __nv_bfloat16* wl, int tid)
{
#pragma unroll
    for (int i = 0; i < 8; ++i) {
        int idx = i * 256 + tid;          // 2048 16B-groups
        int row = idx >> 4, c8 = idx & 15;
        uint32_t off = (row * RS + c8 * 8) * 2;
        cp16(Wh + off, wh + row * 128 + c8 * 8);
        cp16(Wl + off, wl + row * 128 + c8 * 8);
    }
}

// ---------------- weight prep ----------------
__global__ void prep_kernel(const float* __restrict__ W1, const float* __restrict__ W2) {
    int i = blockIdx.x * blockDim.x + threadIdx.x;
    if (i < 384 * 128) {
        float v = W1[i];
        __nv_bfloat16 h = __float2bfloat16(v);
        g_W1_hi[i] = h;
        g_W1_lo[i] = __float2bfloat16(v - __bfloat162float(h));
    }
    if (i < 128 * 128) {
        float v = W2[i];
        __nv_bfloat16 h = __float2bfloat16(v);
        g_W2_hi[i] = h;
        g_W2_lo[i] = __float2bfloat16(v - __bfloat162float(h));
    }
}

// ---------------- main fused kernel ----------------
__global__ void __launch_bounds__(THREADS, 2)
edgeblock_mma(const float* __restrict__ cell,
              const float* __restrict__ edge,
              const float* __restrict__ b1,
              const float* __restrict__ b2,
              const int*   __restrict__ eidx,
              float* __restrict__ out,
              int E)
{
    extern __shared__ __align__(128) __nv_bfloat16 sm[];
    __nv_bfloat16* Ah = sm;
    __nv_bfloat16* Al = sm + A_ELEMS;
    const uint32_t sb   = smem_u32(sm);
    const uint32_t Ah_u = sb;
    const uint32_t Al_u = sb + A_BYTES;
    const uint32_t Wh_u = sb + 2 * A_BYTES;
    const uint32_t Wl_u = sb + 2 * A_BYTES + W_BYTES;

    const int tid = threadIdx.x, wid = tid >> 5, lane = tid & 31;
    const int wm = wid & 1, wn = wid >> 1;      // 2 x 4 warp grid, 32x32 tiles
    const int e0 = blockIdx.x * TILE_M;

    // this thread's fixed gather coordinates: 8 (row, c4) pairs
    const int g_row = tid >> 5;     // rows g_row, g_row+8, ... g_row+56
    const int g_c4  = tid & 31;

    float acc[2][4][4];
#pragma unroll
    for (int t = 0; t < 2; ++t)
#pragma unroll
        for (int j = 0; j < 4; ++j)
#pragma unroll
            for (int c = 0; c < 4; ++c) acc[t][j][c] = 0.0f;

    // ===== GEMM1: 3 K-chunks of 128 =====
#pragma unroll 1
    for (int ch = 0; ch < 3; ++ch) {
        // prefetch W chunk (async)
        stage_w(Wh_u, Wl_u,
                g_W1_hi + (size_t)ch * 128 * 128,
                g_W1_lo + (size_t)ch * 128 * 128, tid);
        CP_COMMIT();

        // --- batched gather: 8 independent LDG.128 in flight (MLP 8) ---
        const float* bases[8];
#pragma unroll
        for (int i = 0; i < 8; ++i) {
            int row = g_row + i * 8;
            int e = e0 + row; int eL = (e < E) ? e : (E - 1);
            if (ch == 0)      bases[i] = cell + (size_t)__ldg(&eidx[eL]) * 128;
            else if (ch == 1) bases[i] = cell + (size_t)__ldg(&eidx[E + eL]) * 128;
            else              bases[i] = edge + (size_t)eL * 128;
        }
        float4 v[8];
#pragma unroll
        for (int i = 0; i < 8; ++i)
            v[i] = reinterpret_cast<const float4*>(bases[i])[g_c4];
#pragma unroll
        for (int i = 0; i < 8; ++i) {
            int row = g_row + i * 8;
            __nv_bfloat162 h0 = __float22bfloat162_rn(make_float2(v[i].x, v[i].y));
            __nv_bfloat162 h1 = __float22bfloat162_rn(make_float2(v[i].z, v[i].w));
            __nv_bfloat162 l0 = __float22bfloat162_rn(make_float2(
                v[i].x - __bfloat162float(h0.x), v[i].y - __bfloat162float(h0.y)));
            __nv_bfloat162 l1 = __float22bfloat162_rn(make_float2(
                v[i].z - __bfloat162float(h1.x), v[i].w - __bfloat162float(h1.y)));
            uint64_t hh = ((uint64_t)*reinterpret_cast<uint32_t*>(&h1) << 32) |
                           *reinterpret_cast<uint32_t*>(&h0);
            uint64_t ll = ((uint64_t)*reinterpret_cast<uint32_t*>(&l1) << 32) |
                           *reinterpret_cast<uint32_t*>(&l0);
            int off = row * RS + g_c4 * 4;
            *reinterpret_cast<uint64_t*>(Ah + off) = hh;
            *reinterpret_cast<uint64_t*>(Al + off) = ll;
        }

        CP_WAIT0();
        __syncthreads();
        gemm_chunk(Ah_u, Al_u, Wh_u, Wl_u, acc, wm, wn, lane);
        __syncthreads();
    }

    // ===== epilogue1: h = relu(acc+b1) split -> A tiles; prefetch W2 =====
    stage_w(Wh_u, Wl_u, g_W2_hi, g_W2_lo, tid);
    CP_COMMIT();
    {
        const int colb = wn * 32 + (lane & 3) * 2;
        const int rowb = wm * 32 + (lane >> 2);
#pragma unroll
        for (int t = 0; t < 2; ++t)
#pragma unroll
            for (int j = 0; j < 4; ++j) {
                int col = colb + j * 8;
                float bx = __ldg(&b1[col]), by = __ldg(&b1[col + 1]);
#pragma unroll
                for (int half = 0; half < 2; ++half) {
                    int row = rowb + t * 16 + half * 8;
                    float x = fmaxf(acc[t][j][2 * half]     + bx, 0.0f);
                    float y = fmaxf(acc[t][j][2 * half + 1] + by, 0.0f);
                    __nv_bfloat162 h2 = __float22bfloat162_rn(make_float2(x, y));
                    __nv_bfloat162 l2 = __float22bfloat162_rn(make_float2(
                        x - __bfloat162float(h2.x), y - __bfloat162float(h2.y)));
                    int off = row * RS + col;
                    *reinterpret_cast<uint32_t*>(Ah + off) = *reinterpret_cast<uint32_t*>(&h2);
                    *reinterpret_cast<uint32_t*>(Al + off) = *reinterpret_cast<uint32_t*>(&l2);
                }
            }
#pragma unroll
        for (int t = 0; t < 2; ++t)
#pragma unroll
            for (int j = 0; j < 4; ++j)
#pragma unroll
                for (int c = 0; c < 4; ++c) acc[t][j][c] = 0.0f;
    }
    CP_WAIT0();
    __syncthreads();

    // ===== GEMM2 =====
    gemm_chunk(Ah_u, Al_u, Wh_u, Wl_u, acc, wm, wn, lane);

    // ===== epilogue2: + b2, store =====
    {
        const int colb = wn * 32 + (lane & 3) * 2;
        const int rowb = wm * 32 + (lane >> 2);
#pragma unroll
        for (int t = 0; t < 2; ++t)
#pragma unroll
            for (int j = 0; j < 4; ++j) {
                int col = colb + j * 8;
                float bx = __ldg(&b2[col]), by = __ldg(&b2[col + 1]);
#pragma unroll
                for (int half = 0; half < 2; ++half) {
                    int row = rowb + t * 16 + half * 8;
                    int e = e0 + row;
                    if (e < E) {
                        float2 o = make_float2(acc[t][j][2 * half] + bx,
                                               acc[t][j][2 * half + 1] + by);
                        *reinterpret_cast<float2*>(out + (size_t)e * 128 + col) = o;
                    }
                }
            }
    }
}

extern "C" void kernel_launch(void* const* d_in, const int* in_sizes, int n_in,
                              void* d_out, int out_size) {
    const float* cell = (const float*)d_in[0];   // [50000,128]
    const float* edge = (const float*)d_in[1];   // [E,128]
    const float* W1   = (const float*)d_in[2];   // [384,128]
    const float* b1   = (const float*)d_in[3];   // [128]
    const float* W2   = (const float*)d_in[4];   // [128,128]
    const float* b2   = (const float*)d_in[5];   // [128]
    const int*   eidx = (const int*)d_in[6];     // [2,E]
    float* out = (float*)d_out;

    int E = in_sizes[6] / 2;

    prep_kernel<<<(384 * 128 + 255) / 256, 256>>>(W1, W2);

    cudaFuncSetAttribute(edgeblock_mma,
                         cudaFuncAttributeMaxDynamicSharedMemorySize, SMEM_BYTES);
    int grid = (E + TILE_M - 1) / TILE_M;
    edgeblock_mma<<<grid, THREADS, SMEM_BYTES>>>(cell, edge, b1, b2, eidx, out, E);
}

// round 9
// speedup vs baseline: 3.7806x; 1.1114x over previous
#include <cuda_runtime.h>
#include <cuda_bf16.h>
#include <cstdint>

// EdgeBlock: out = relu(concat(cell[src],cell[dst],edge) @ W1 + b1) @ W2 + b2
// v4: single-pass tf32 mma.m16n8k8 (err budget 1e-3 >> tf32's ~5e-4),
//     TILE_M=64, 2 CTAs/SM, cp.async weight staging, MLP-8 batched gather.

#define THREADS 256
#define TILE_M  64
#define RSA     132                     // f32 per smem row (128 + 4 pad; 33x16B odd)
#define A_BYTES (64 * RSA * 4)          // 33792
#define W_BYTES (128 * RSA * 4)        // 67584
#define SMEM_BYTES (A_BYTES + W_BYTES)  // 101376

// pre-transposed tf32-rounded weights, n-major: W1T[n][k]
__device__ float g_W1T[128 * 384];
__device__ float g_W2T[128 * 128];

// ---------------- helpers ----------------
__device__ __forceinline__ uint32_t smem_u32(const void* p) {
    uint32_t a;
    asm("{ .reg .u64 t; cvta.to.shared.u64 t, %1; cvt.u32.u64 %0, t; }" : "=r"(a) : "l"(p));
    return a;
}
__device__ __forceinline__ uint32_t tf32_bits(float x) {
    uint32_t r;
    asm("cvt.rna.tf32.f32 %0, %1;" : "=r"(r) : "f"(x));
    return r;
}
__device__ __forceinline__ float tf32f(float x) { return __uint_as_float(tf32_bits(x)); }

__device__ __forceinline__ void ldm_x4(uint32_t* r, uint32_t addr) {
    asm volatile("ldmatrix.sync.aligned.m8n8.x4.shared.b16 {%0,%1,%2,%3}, [%4];"
                 : "=r"(r[0]), "=r"(r[1]), "=r"(r[2]), "=r"(r[3]) : "r"(addr));
}
__device__ __forceinline__ void ldm_x2(uint32_t* r, uint32_t addr) {
    asm volatile("ldmatrix.sync.aligned.m8n8.x2.shared.b16 {%0,%1}, [%2];"
                 : "=r"(r[0]), "=r"(r[1]) : "r"(addr));
}
__device__ __forceinline__ void mma_tf32(float* d, const uint32_t* a, const uint32_t* b) {
    asm volatile(
        "mma.sync.aligned.m16n8k8.row.col.f32.tf32.tf32.f32 "
        "{%0,%1,%2,%3}, {%4,%5,%6,%7}, {%8,%9}, {%0,%1,%2,%3};"
        : "+f"(d[0]), "+f"(d[1]), "+f"(d[2]), "+f"(d[3])
        : "r"(a[0]), "r"(a[1]), "r"(a[2]), "r"(a[3]), "r"(b[0]), "r"(b[1]));
}
__device__ __forceinline__ void cp16(uint32_t dst, const void* src) {
    asm volatile("cp.async.cg.shared.global [%0], [%1], 16;" :: "r"(dst), "l"(src));
}
#define CP_COMMIT() asm volatile("cp.async.commit_group;" ::: "memory")
#define CP_WAIT0()  asm volatile("cp.async.wait_group 0;" ::: "memory")

// one warp's share of a 64x128 (M x N) x K=128 chunk in tf32, 16 k8-steps
__device__ __forceinline__ void gemm_chunk(uint32_t At, uint32_t Wt,
                                           float acc[2][4][4],
                                           int wm, int wn, int lane)
{
    const int lr  = lane & 15;             // A: row within 16
    const int lkA = (lane >> 4) * 4;       // A: b32 k-offset (0/4)
    const int ln  = lane & 15;             // B: use low-16 pattern for all lanes
    const int bn  = ln & 7;                // B: n within 8
    const int lkB = (ln >> 3) * 4;         // B: b32 k-offset (0/4)
#pragma unroll 2
    for (int kk = 0; kk < 16; ++kk) {
        uint32_t a[2][4];
#pragma unroll
        for (int t = 0; t < 2; ++t)
            ldm_x4(a[t], At + ((wm * 32 + t * 16 + lr) * RSA + kk * 8 + lkA) * 4);
        uint32_t b[4][2];
#pragma unroll
        for (int j = 0; j < 4; ++j)
            ldm_x2(b[j], Wt + ((wn * 32 + j * 8 + bn) * RSA + kk * 8 + lkB) * 4);
#pragma unroll
        for (int t = 0; t < 2; ++t)
#pragma unroll
            for (int j = 0; j < 4; ++j)
                mma_tf32(acc[t][j], a[t], b[j]);
    }
}

// stage one 128n x 128k f32 tile via cp.async (src row stride in floats)
__device__ __forceinline__ void stage_w(uint32_t Wt, const float* src,
                                        int src_stride, int tid)
{
#pragma unroll
    for (int i = 0; i < 16; ++i) {
        int idx = i * 256 + tid;          // 4096 16B-groups
        int row = idx >> 5, c4 = idx & 31;
        cp16(Wt + (row * RSA + c4 * 4) * 4, src + row * src_stride + c4 * 4);
    }
}

// ---------------- weight prep: transpose to n-major + tf32 round ----------------
__global__ void prep_kernel(const float* __restrict__ W1, const float* __restrict__ W2) {
    int i = blockIdx.x * blockDim.x + threadIdx.x;
    if (i < 384 * 128) {
        int k = i >> 7, n = i & 127;
        g_W1T[n * 384 + k] = tf32f(W1[i]);
    }
    if (i < 128 * 128) {
        int k = i >> 7, n = i & 127;
        g_W2T[n * 128 + k] = tf32f(W2[i]);
    }
}

// ---------------- main fused kernel ----------------
__global__ void __launch_bounds__(THREADS, 2)
edgeblock_mma(const float* __restrict__ cell,
              const float* __restrict__ edge,
              const float* __restrict__ b1,
              const float* __restrict__ b2,
              const int*   __restrict__ eidx,
              float* __restrict__ out,
              int E)
{
    extern __shared__ __align__(16) float sm[];
    float* At = sm;                                  // [64][RSA]
    const uint32_t sb   = smem_u32(sm);
    const uint32_t At_u = sb;
    const uint32_t Wt_u = sb + A_BYTES;

    const int tid = threadIdx.x, wid = tid >> 5, lane = tid & 31;
    const int wm = wid & 1, wn = wid >> 1;      // 2 x 4 warp grid, 32x32 tiles
    const int e0 = blockIdx.x * TILE_M;

    const int g_row = tid >> 5;     // gather rows g_row + 8i
    const int g_c4  = tid & 31;

    float acc[2][4][4];
#pragma unroll
    for (int t = 0; t < 2; ++t)
#pragma unroll
        for (int j = 0; j < 4; ++j)
#pragma unroll
            for (int c = 0; c < 4; ++c) acc[t][j][c] = 0.0f;

    // ===== GEMM1: 3 K-chunks of 128 =====
#pragma unroll 1
    for (int ch = 0; ch < 3; ++ch) {
        stage_w(Wt_u, g_W1T + ch * 128, 384, tid);   // async W chunk (n-major cols ch*128..)
        CP_COMMIT();

        // batched gather (MLP 8), tf32 round, single STS.128 per row-part
        const float* bases[8];
#pragma unroll
        for (int i = 0; i < 8; ++i) {
            int row = g_row + i * 8;
            int e = e0 + row; int eL = (e < E) ? e : (E - 1);
            if (ch == 0)      bases[i] = cell + (size_t)__ldg(&eidx[eL]) * 128;
            else if (ch == 1) bases[i] = cell + (size_t)__ldg(&eidx[E + eL]) * 128;
            else              bases[i] = edge + (size_t)eL * 128;
        }
        float4 v[8];
#pragma unroll
        for (int i = 0; i < 8; ++i)
            v[i] = reinterpret_cast<const float4*>(bases[i])[g_c4];
#pragma unroll
        for (int i = 0; i < 8; ++i) {
            int row = g_row + i * 8;
            float4 q;
            q.x = tf32f(v[i].x); q.y = tf32f(v[i].y);
            q.z = tf32f(v[i].z); q.w = tf32f(v[i].w);
            *reinterpret_cast<float4*>(&At[row * RSA + g_c4 * 4]) = q;
        }

        CP_WAIT0();
        __syncthreads();
        gemm_chunk(At_u, Wt_u, acc, wm, wn, lane);
        __syncthreads();
    }

    // ===== epilogue1: h = relu(acc+b1) -> tf32 -> A tile; prefetch W2 =====
    stage_w(Wt_u, g_W2T, 128, tid);
    CP_COMMIT();
    {
        const int colb = wn * 32 + (lane & 3) * 2;
        const int rowb = wm * 32 + (lane >> 2);
#pragma unroll
        for (int t = 0; t < 2; ++t)
#pragma unroll
            for (int j = 0; j < 4; ++j) {
                int col = colb + j * 8;
                float bx = __ldg(&b1[col]), by = __ldg(&b1[col + 1]);
#pragma unroll
                for (int half = 0; half < 2; ++half) {
                    int row = rowb + t * 16 + half * 8;
                    float2 h2;
                    h2.x = tf32f(fmaxf(acc[t][j][2 * half]     + bx, 0.0f));
                    h2.y = tf32f(fmaxf(acc[t][j][2 * half + 1] + by, 0.0f));
                    *reinterpret_cast<float2*>(&At[row * RSA + col]) = h2;
                }
            }
#pragma unroll
        for (int t = 0; t < 2; ++t)
#pragma unroll
            for (int j = 0; j < 4; ++j)
#pragma unroll
                for (int c = 0; c < 4; ++c) acc[t][j][c] = 0.0f;
    }
    CP_WAIT0();
    __syncthreads();

    // ===== GEMM2 =====
    gemm_chunk(At_u, Wt_u, acc, wm, wn, lane);

    // ===== epilogue2: + b2, store =====
    {
        const int colb = wn * 32 + (lane & 3) * 2;
        const int rowb = wm * 32 + (lane >> 2);
#pragma unroll
        for (int t = 0; t < 2; ++t)
#pragma unroll
            for (int j = 0; j < 4; ++j) {
                int col = colb + j * 8;
                float bx = __ldg(&b2[col]), by = __ldg(&b2[col + 1]);
#pragma unroll
                for (int half = 0; half < 2; ++half) {
                    int row = rowb + t * 16 + half * 8;
                    int e = e0 + row;
                    if (e < E) {
                        float2 o = make_float2(acc[t][j][2 * half] + bx,
                                               acc[t][j][2 * half + 1] + by);
                        *reinterpret_cast<float2*>(out + (size_t)e * 128 + col) = o;
                    }
                }
            }
    }
}

extern "C" void kernel_launch(void* const* d_in, const int* in_sizes, int n_in,
                              void* d_out, int out_size) {
    const float* cell = (const float*)d_in[0];   // [50000,128]
    const float* edge = (const float*)d_in[1];   // [E,128]
    const float* W1   = (const float*)d_in[2];   // [384,128]
    const float* b1   = (const float*)d_in[3];   // [128]
    const float* W2   = (const float*)d_in[4];   // [128,128]
    const float* b2   = (const float*)d_in[5];   // [128]
    const int*   eidx = (const int*)d_in[6];     // [2,E]
    float* out = (float*)d_out;

    int E = in_sizes[6] / 2;

    prep_kernel<<<(384 * 128 + 255) / 256, 256>>>(W1, W2);

    cudaFuncSetAttribute(edgeblock_mma,
                         cudaFuncAttributeMaxDynamicSharedMemorySize, SMEM_BYTES);
    int grid = (E + TILE_M - 1) / TILE_M;
    edgeblock_mma<<<grid, THREADS, SMEM_BYTES>>>(cell, edge, b1, b2, eidx, out, E);
}

// round 10
// speedup vs baseline: 4.5197x; 1.1955x over previous
#include <cuda_runtime.h>
#include <cstdint>

// EdgeBlock: out = relu(concat(cell[src],cell[dst],edge) @ W1 + b1) @ W2 + b2
// v5: tf32 mma.m16n8k8, warp tile 32x64 (1.5 LDS-wf/mma), XOR-swizzled smem
//     (no padding), 128 thr/CTA, 2 CTAs/SM, cp.async W staging, MLP-8 gather.

#define THREADS 128
#define TILE_M  64
#define A_BYTES 32768                   // 64 x 128 f32, swizzled
#define W_BYTES 65536                   // 128 x 128 f32, swizzled
#define SMEM_BYTES (A_BYTES + W_BYTES)  // 98304 -> 2 CTAs/SM

// pre-transposed tf32-rounded weights, n-major: W1T[n][k]
__device__ float g_W1T[128 * 384];
__device__ float g_W2T[128 * 128];

// ---------------- helpers ----------------
__device__ __forceinline__ uint32_t smem_u32(const void* p) {
    uint32_t a;
    asm("{ .reg .u64 t; cvta.to.shared.u64 t, %1; cvt.u32.u64 %0, t; }" : "=r"(a) : "l"(p));
    return a;
}
__device__ __forceinline__ float tf32f(float x) {
    uint32_t r;
    asm("cvt.rna.tf32.f32 %0, %1;" : "=r"(r) : "f"(x));
    return __uint_as_float(r);
}
// swizzled byte offset within a [rows x 128 f32] tile (512B rows)
__device__ __forceinline__ uint32_t sw_off(int row, int kf32) {
    uint32_t c = ((uint32_t)kf32 >> 2) ^ ((uint32_t)row & 7);
    return (uint32_t)row * 512u + c * 16u + ((uint32_t)kf32 & 3u) * 4u;
}
__device__ __forceinline__ void ldm_x4(uint32_t* r, uint32_t addr) {
    asm volatile("ldmatrix.sync.aligned.m8n8.x4.shared.b16 {%0,%1,%2,%3}, [%4];"
                 : "=r"(r[0]), "=r"(r[1]), "=r"(r[2]), "=r"(r[3]) : "r"(addr));
}
__device__ __forceinline__ void mma_tf32(float* d, const uint32_t* a, const uint32_t* b) {
    asm volatile(
        "mma.sync.aligned.m16n8k8.row.col.f32.tf32.tf32.f32 "
        "{%0,%1,%2,%3}, {%4,%5,%6,%7}, {%8,%9}, {%0,%1,%2,%3};"
        : "+f"(d[0]), "+f"(d[1]), "+f"(d[2]), "+f"(d[3])
        : "r"(a[0]), "r"(a[1]), "r"(a[2]), "r"(a[3]), "r"(b[0]), "r"(b[1]));
}
__device__ __forceinline__ void cp16(uint32_t dst, const void* src) {
    asm volatile("cp.async.cg.shared.global [%0], [%1], 16;" :: "r"(dst), "l"(src));
}
#define CP_COMMIT() asm volatile("cp.async.commit_group;" ::: "memory")
#define CP_WAIT0()  asm volatile("cp.async.wait_group 0;" ::: "memory")

// one warp's 32x64 share of a 64(M) x 128(N) x 128(K) tf32 chunk
__device__ __forceinline__ void gemm_chunk(uint32_t At, uint32_t Wt,
                                           float acc[2][8][4],
                                           int wm, int wn, int lane)
{
    const int sub = lane >> 3, l7 = lane & 7;
    const int arow = wm * 32 + (sub & 1) * 8 + l7;     // + t*16
    const int akof = (sub >> 1) * 4;                   // + kk*8
    const int brow = wn * 64 + (sub >> 1) * 8 + l7;    // + p*16
    const int bkof = (sub & 1) * 4;                    // + kk*8
#pragma unroll 2
    for (int kk = 0; kk < 16; ++kk) {
        uint32_t a[2][4];
#pragma unroll
        for (int t = 0; t < 2; ++t)
            ldm_x4(a[t], At + sw_off(arow + t * 16, kk * 8 + akof));
        uint32_t b[4][4];
#pragma unroll
        for (int p = 0; p < 4; ++p)
            ldm_x4(b[p], Wt + sw_off(brow + p * 16, kk * 8 + bkof));
#pragma unroll
        for (int t = 0; t < 2; ++t)
#pragma unroll
            for (int p = 0; p < 4; ++p) {
                mma_tf32(acc[t][2 * p],     a[t], &b[p][0]);
                mma_tf32(acc[t][2 * p + 1], a[t], &b[p][2]);
            }
    }
}

// stage one 128n x 128k f32 tile via cp.async into swizzled layout
__device__ __forceinline__ void stage_w(uint32_t Wt, const float* src,
                                        int src_stride, int tid)
{
#pragma unroll
    for (int i = 0; i < 32; ++i) {
        int idx = i * 128 + tid;          // 4096 16B-groups
        int row = idx >> 5, c4 = idx & 31;
        cp16(Wt + sw_off(row, c4 * 4), src + row * src_stride + c4 * 4);
    }
}

// ---------------- weight prep: transpose to n-major + tf32 round ----------------
__global__ void prep_kernel(const float* __restrict__ W1, const float* __restrict__ W2) {
    int i = blockIdx.x * blockDim.x + threadIdx.x;
    if (i < 384 * 128) {
        int k = i >> 7, n = i & 127;
        g_W1T[n * 384 + k] = tf32f(W1[i]);
    }
    if (i < 128 * 128) {
        int k = i >> 7, n = i & 127;
        g_W2T[n * 128 + k] = tf32f(W2[i]);
    }
}

// ---------------- main fused kernel ----------------
__global__ void __launch_bounds__(THREADS, 2)
edgeblock_mma(const float* __restrict__ cell,
              const float* __restrict__ edge,
              const float* __restrict__ b1,
              const float* __restrict__ b2,
              const int*   __restrict__ eidx,
              float* __restrict__ out,
              int E)
{
    extern __shared__ __align__(16) char sm[];
    char* At = sm;
    const uint32_t sb   = smem_u32(sm);
    const uint32_t At_u = sb;
    const uint32_t Wt_u = sb + A_BYTES;

    const int tid = threadIdx.x, wid = tid >> 5, lane = tid & 31;
    const int wm = wid & 1, wn = wid >> 1;      // 2m x 2n grid, 32x64 warp tiles
    const int e0 = blockIdx.x * TILE_M;

    const int g_rsub = wid * 4 + (lane >> 3);   // row within 16-row group
    const int g_l7   = lane & 7;

    float acc[2][8][4];
#pragma unroll
    for (int t = 0; t < 2; ++t)
#pragma unroll
        for (int j = 0; j < 8; ++j)
#pragma unroll
            for (int c = 0; c < 4; ++c) acc[t][j][c] = 0.0f;

    // ===== GEMM1: 3 K-chunks of 128 =====
#pragma unroll 1
    for (int ch = 0; ch < 3; ++ch) {
        stage_w(Wt_u, g_W1T + ch * 128, 384, tid);   // async W chunk
        CP_COMMIT();

        // gather 64 rows x 128 f32: two MLP-8 batches of 2 row-groups each
#pragma unroll 1
        for (int jp = 0; jp < 2; ++jp) {
            int rows[2]; const float* bases[2];
#pragma unroll
            for (int jj = 0; jj < 2; ++jj) {
                int row = (jp * 2 + jj) * 16 + g_rsub;
                rows[jj] = row;
                int e = e0 + row; int eL = (e < E) ? e : (E - 1);
                if (ch == 0)      bases[jj] = cell + (size_t)__ldg(&eidx[eL]) * 128;
                else if (ch == 1) bases[jj] = cell + (size_t)__ldg(&eidx[E + eL]) * 128;
                else              bases[jj] = edge + (size_t)eL * 128;
            }
            float4 v[8];
#pragma unroll
            for (int jj = 0; jj < 2; ++jj)
#pragma unroll
                for (int i = 0; i < 4; ++i)
                    v[jj * 4 + i] = reinterpret_cast<const float4*>(bases[jj])[g_l7 + 8 * i];
#pragma unroll
            for (int jj = 0; jj < 2; ++jj)
#pragma unroll
                for (int i = 0; i < 4; ++i) {
                    int c4 = g_l7 + 8 * i;
                    float4 q;
                    q.x = tf32f(v[jj * 4 + i].x); q.y = tf32f(v[jj * 4 + i].y);
                    q.z = tf32f(v[jj * 4 + i].z); q.w = tf32f(v[jj * 4 + i].w);
                    *reinterpret_cast<float4*>(At + sw_off(rows[jj], c4 * 4)) = q;
                }
        }

        CP_WAIT0();
        __syncthreads();
        gemm_chunk(At_u, Wt_u, acc, wm, wn, lane);
        __syncthreads();
    }

    // ===== epilogue1: h = relu(acc+b1) -> tf32 -> A tile; prefetch W2 =====
    stage_w(Wt_u, g_W2T, 128, tid);
    CP_COMMIT();
    {
        const int colb = wn * 64 + (lane & 3) * 2;
        const int rowb = wm * 32 + (lane >> 2);
#pragma unroll
        for (int t = 0; t < 2; ++t)
#pragma unroll
            for (int j = 0; j < 8; ++j) {
                int col = colb + j * 8;
                float bx = __ldg(&b1[col]), by = __ldg(&b1[col + 1]);
#pragma unroll
                for (int half = 0; half < 2; ++half) {
                    int row = rowb + t * 16 + half * 8;
                    float2 h2;
                    h2.x = tf32f(fmaxf(acc[t][j][2 * half]     + bx, 0.0f));
                    h2.y = tf32f(fmaxf(acc[t][j][2 * half + 1] + by, 0.0f));
                    *reinterpret_cast<float2*>(At + sw_off(row, col)) = h2;
                }
            }
#pragma unroll
        for (int t = 0; t < 2; ++t)
#pragma unroll
            for (int j = 0; j < 8; ++j)
#pragma unroll
                for (int c = 0; c < 4; ++c) acc[t][j][c] = 0.0f;
    }
    CP_WAIT0();
    __syncthreads();

    // ===== GEMM2: [64 x 128] @ W2 =====
    gemm_chunk(At_u, Wt_u, acc, wm, wn, lane);

    // ===== epilogue2: + b2, store =====
    {
        const int colb = wn * 64 + (lane & 3) * 2;
        const int rowb = wm * 32 + (lane >> 2);
#pragma unroll
        for (int t = 0; t < 2; ++t)
#pragma unroll
            for (int j = 0; j < 8; ++j) {
                int col = colb + j * 8;
                float bx = __ldg(&b2[col]), by = __ldg(&b2[col + 1]);
#pragma unroll
                for (int half = 0; half < 2; ++half) {
                    int row = rowb + t * 16 + half * 8;
                    int e = e0 + row;
                    if (e < E) {
                        float2 o = make_float2(acc[t][j][2 * half] + bx,
                                               acc[t][j][2 * half + 1] + by);
                        *reinterpret_cast<float2*>(out + (size_t)e * 128 + col) = o;
                    }
                }
            }
    }
}

extern "C" void kernel_launch(void* const* d_in, const int* in_sizes, int n_in,
                              void* d_out, int out_size) {
    const float* cell = (const float*)d_in[0];   // [50000,128]
    const float* edge = (const float*)d_in[1];   // [E,128]
    const float* W1   = (const float*)d_in[2];   // [384,128]
    const float* b1   = (const float*)d_in[3];   // [128]
    const float* W2   = (const float*)d_in[4];   // [128,128]
    const float* b2   = (const float*)d_in[5];   // [128]
    const int*   eidx = (const int*)d_in[6];     // [2,E]
    float* out = (float*)d_out;

    int E = in_sizes[6] / 2;

    prep_kernel<<<(384 * 128 + 255) / 256, 256>>>(W1, W2);

    cudaFuncSetAttribute(edgeblock_mma,
                         cudaFuncAttributeMaxDynamicSharedMemorySize, SMEM_BYTES);
    int grid = (E + TILE_M - 1) / TILE_M;
    edgeblock_mma<<<grid, THREADS, SMEM_BYTES>>>(cell, edge, b1, b2, eidx, out, E);
}

// round 11
// speedup vs baseline: 8.0182x; 1.7741x over previous
#include <cuda_runtime.h>
#include <cuda_fp16.h>
#include <cstdint>

// EdgeBlock: out = relu(concat(cell[src],cell[dst],edge) @ W1 + b1) @ W2 + b2
// v6: single-pass fp16 mma.m16n8k16 (same 10-bit mantissa as tf32, half the
//     instructions), warp tile 32x64, XOR-swizzled fp16 smem (48 KB/CTA,
//     3 CTAs/SM), cp.async W staging, MLP-8 batched gather.

#define THREADS 128
#define TILE_M  64
#define A_BYTES 16384                   // 64 x 128 fp16, swizzled (256B rows)
#define W_BYTES 32768                   // 128 x 128 fp16, swizzled
#define SMEM_BYTES (A_BYTES + W_BYTES)  // 49152 -> 3+ CTAs/SM

// pre-transposed fp16 weights, n-major: W1T[n][k]
__device__ __half g_W1T[128 * 384];
__device__ __half g_W2T[128 * 128];

// swizzled byte offset in a [rows x 128 fp16] tile (256B rows, 16B chunks)
// colh = fp16 column index
#define SWA(row, colh) \
    ((uint32_t)(row) * 256u + (((((uint32_t)(colh)) >> 3) ^ ((uint32_t)(row) & 7u)) << 4) \
     + (((uint32_t)(colh) & 7u) << 1))

// ---------------- helpers ----------------
__device__ __forceinline__ uint32_t smem_u32(const void* p) {
    uint32_t a;
    asm("{ .reg .u64 t; cvta.to.shared.u64 t, %1; cvt.u32.u64 %0, t; }" : "=r"(a) : "l"(p));
    return a;
}
__device__ __forceinline__ void ldm_x4(uint32_t* r, uint32_t addr) {
    asm volatile("ldmatrix.sync.aligned.m8n8.x4.shared.b16 {%0,%1,%2,%3}, [%4];"
                 : "=r"(r[0]), "=r"(r[1]), "=r"(r[2]), "=r"(r[3]) : "r"(addr));
}
__device__ __forceinline__ void mma_f16(float* d, const uint32_t* a, const uint32_t* b) {
    asm volatile(
        "mma.sync.aligned.m16n8k16.row.col.f32.f16.f16.f32 "
        "{%0,%1,%2,%3}, {%4,%5,%6,%7}, {%8,%9}, {%0,%1,%2,%3};"
        : "+f"(d[0]), "+f"(d[1]), "+f"(d[2]), "+f"(d[3])
        : "r"(a[0]), "r"(a[1]), "r"(a[2]), "r"(a[3]), "r"(b[0]), "r"(b[1]));
}
__device__ __forceinline__ void cp16(uint32_t dst, const void* src) {
    asm volatile("cp.async.cg.shared.global [%0], [%1], 16;" :: "r"(dst), "l"(src));
}
#define CP_COMMIT() asm volatile("cp.async.commit_group;" ::: "memory")
#define CP_WAIT0()  asm volatile("cp.async.wait_group 0;" ::: "memory")

// one warp's 32x64 share of a 64(M) x 128(N) x 128(K) fp16 chunk, 8 k16-steps
__device__ __forceinline__ void gemm_chunk(uint32_t At, uint32_t Wt,
                                           float acc[2][8][4],
                                           int wm, int wn, int lane)
{
    const int sub = lane >> 3, l7 = lane & 7;
    const int arow = wm * 32 + (sub & 1) * 8 + l7;     // + t*16
    const int akol = (sub >> 1) * 8;                   // + kk*16
    const int brow = wn * 64 + (sub >> 1) * 8 + l7;    // + p*16
    const int bkol = (sub & 1) * 8;                    // + kk*16
#pragma unroll 2
    for (int kk = 0; kk < 8; ++kk) {
        uint32_t a[2][4];
#pragma unroll
        for (int t = 0; t < 2; ++t)
            ldm_x4(a[t], At + SWA(arow + t * 16, kk * 16 + akol));
        uint32_t b[4][4];
#pragma unroll
        for (int p = 0; p < 4; ++p)
            ldm_x4(b[p], Wt + SWA(brow + p * 16, kk * 16 + bkol));
#pragma unroll
        for (int t = 0; t < 2; ++t)
#pragma unroll
            for (int p = 0; p < 4; ++p) {
                mma_f16(acc[t][2 * p],     a[t], &b[p][0]);
                mma_f16(acc[t][2 * p + 1], a[t], &b[p][2]);
            }
    }
}

// stage one 128n x 128k fp16 tile via cp.async into swizzled layout
__device__ __forceinline__ void stage_w(uint32_t Wt, const __half* src,
                                        int src_stride, int tid)
{
#pragma unroll
    for (int i = 0; i < 16; ++i) {
        int idx = i * 128 + tid;          // 2048 16B-groups
        int row = idx >> 4, c8 = idx & 15;
        cp16(Wt + SWA(row, c8 * 8), src + row * src_stride + c8 * 8);
    }
}

// ---------------- weight prep: transpose to n-major + fp16 ----------------
__global__ void prep_kernel(const float* __restrict__ W1, const float* __restrict__ W2) {
    int i = blockIdx.x * blockDim.x + threadIdx.x;
    if (i < 384 * 128) {
        int k = i >> 7, n = i & 127;
        g_W1T[n * 384 + k] = __float2half_rn(W1[i]);
    }
    if (i < 128 * 128) {
        int k = i >> 7, n = i & 127;
        g_W2T[n * 128 + k] = __float2half_rn(W2[i]);
    }
}

// ---------------- main fused kernel ----------------
__global__ void __launch_bounds__(THREADS, 3)
edgeblock_mma(const float* __restrict__ cell,
              const float* __restrict__ edge,
              const float* __restrict__ b1,
              const float* __restrict__ b2,
              const int*   __restrict__ eidx,
              float* __restrict__ out,
              int E)
{
    extern __shared__ __align__(16) char sm[];
    char* At = sm;
    const uint32_t sb   = smem_u32(sm);
    const uint32_t At_u = sb;
    const uint32_t Wt_u = sb + A_BYTES;

    const int tid = threadIdx.x, wid = tid >> 5, lane = tid & 31;
    const int wm = wid & 1, wn = wid >> 1;      // 2m x 2n grid, 32x64 warp tiles
    const int e0 = blockIdx.x * TILE_M;

    const int g_rsub = wid * 4 + (lane >> 3);   // row within 16-row group
    const int g_l7   = lane & 7;

    float acc[2][8][4];
#pragma unroll
    for (int t = 0; t < 2; ++t)
#pragma unroll
        for (int j = 0; j < 8; ++j)
#pragma unroll
            for (int c = 0; c < 4; ++c) acc[t][j][c] = 0.0f;

    // ===== GEMM1: 3 K-chunks of 128 =====
#pragma unroll 1
    for (int ch = 0; ch < 3; ++ch) {
        stage_w(Wt_u, g_W1T + ch * 128, 384, tid);   // async W chunk
        CP_COMMIT();

        // gather 64 rows x 128 f32 -> fp16: two MLP-8 batches
#pragma unroll 1
        for (int jp = 0; jp < 2; ++jp) {
            int rows[2]; const float* bases[2];
#pragma unroll
            for (int jj = 0; jj < 2; ++jj) {
                int row = (jp * 2 + jj) * 16 + g_rsub;
                rows[jj] = row;
                int e = e0 + row; int eL = (e < E) ? e : (E - 1);
                if (ch == 0)      bases[jj] = cell + (size_t)__ldg(&eidx[eL]) * 128;
                else if (ch == 1) bases[jj] = cell + (size_t)__ldg(&eidx[E + eL]) * 128;
                else              bases[jj] = edge + (size_t)eL * 128;
            }
            float4 v[8];
#pragma unroll
            for (int jj = 0; jj < 2; ++jj)
#pragma unroll
                for (int i = 0; i < 4; ++i)
                    v[jj * 4 + i] = reinterpret_cast<const float4*>(bases[jj])[g_l7 + 8 * i];
#pragma unroll
            for (int jj = 0; jj < 2; ++jj)
#pragma unroll
                for (int i = 0; i < 4; ++i) {
                    int c4 = g_l7 + 8 * i;
                    __half2 h0 = __float22half2_rn(make_float2(v[jj * 4 + i].x, v[jj * 4 + i].y));
                    __half2 h1 = __float22half2_rn(make_float2(v[jj * 4 + i].z, v[jj * 4 + i].w));
                    uint64_t q = ((uint64_t)*reinterpret_cast<uint32_t*>(&h1) << 32) |
                                  *reinterpret_cast<uint32_t*>(&h0);
                    *reinterpret_cast<uint64_t*>(At + SWA(rows[jj], c4 * 4)) = q;
                }
        }

        CP_WAIT0();
        __syncthreads();
        gemm_chunk(At_u, Wt_u, acc, wm, wn, lane);
        __syncthreads();
    }

    // ===== epilogue1: h = relu(acc+b1) -> fp16 -> A tile; prefetch W2 =====
    stage_w(Wt_u, g_W2T, 128, tid);
    CP_COMMIT();
    {
        const int colb = wn * 64 + (lane & 3) * 2;
        const int rowb = wm * 32 + (lane >> 2);
#pragma unroll
        for (int t = 0; t < 2; ++t)
#pragma unroll
            for (int j = 0; j < 8; ++j) {
                int col = colb + j * 8;
                float bx = __ldg(&b1[col]), by = __ldg(&b1[col + 1]);
#pragma unroll
                for (int half = 0; half < 2; ++half) {
                    int row = rowb + t * 16 + half * 8;
                    __half2 h2 = __float22half2_rn(make_float2(
                        fmaxf(acc[t][j][2 * half]     + bx, 0.0f),
                        fmaxf(acc[t][j][2 * half + 1] + by, 0.0f)));
                    *reinterpret_cast<uint32_t*>(At + SWA(row, col)) =
                        *reinterpret_cast<uint32_t*>(&h2);
                }
            }
#pragma unroll
        for (int t = 0; t < 2; ++t)
#pragma unroll
            for (int j = 0; j < 8; ++j)
#pragma unroll
                for (int c = 0; c < 4; ++c) acc[t][j][c] = 0.0f;
    }
    CP_WAIT0();
    __syncthreads();

    // ===== GEMM2: [64 x 128] @ W2 =====
    gemm_chunk(At_u, Wt_u, acc, wm, wn, lane);

    // ===== epilogue2: + b2, store =====
    {
        const int colb = wn * 64 + (lane & 3) * 2;
        const int rowb = wm * 32 + (lane >> 2);
#pragma unroll
        for (int t = 0; t < 2; ++t)
#pragma unroll
            for (int j = 0; j < 8; ++j) {
                int col = colb + j * 8;
                float bx = __ldg(&b2[col]), by = __ldg(&b2[col + 1]);
#pragma unroll
                for (int half = 0; half < 2; ++half) {
                    int row = rowb + t * 16 + half * 8;
                    int e = e0 + row;
                    if (e < E) {
                        float2 o = make_float2(acc[t][j][2 * half] + bx,
                                               acc[t][j][2 * half + 1] + by);
                        *reinterpret_cast<float2*>(out + (size_t)e * 128 + col) = o;
                    }
                }
            }
    }
}

extern "C" void kernel_launch(void* const* d_in, const int* in_sizes, int n_in,
                              void* d_out, int out_size) {
    const float* cell = (const float*)d_in[0];   // [50000,128]
    const float* edge = (const float*)d_in[1];   // [E,128]
    const float* W1   = (const float*)d_in[2];   // [384,128]
    const float* b1   = (const float*)d_in[3];   // [128]
    const float* W2   = (const float*)d_in[4];   // [128,128]
    const float* b2   = (const float*)d_in[5];   // [128]
    const int*   eidx = (const int*)d_in[6];     // [2,E]
    float* out = (float*)d_out;

    int E = in_sizes[6] / 2;

    prep_kernel<<<(384 * 128 + 255) / 256, 256>>>(W1, W2);

    cudaFuncSetAttribute(edgeblock_mma,
                         cudaFuncAttributeMaxDynamicSharedMemorySize, SMEM_BYTES);
    int grid = (E + TILE_M - 1) / TILE_M;
    edgeblock_mma<<<grid, THREADS, SMEM_BYTES>>>(cell, edge, b1, b2, eidx, out, E);
}